// round 1
// baseline (speedup 1.0000x reference)
#include <cuda_runtime.h>
#include <math.h>

// Problem constants (fixed shapes from reference)
#define B_  8
#define SQ_ 2048
#define SK_ 2048
#define D_  1024
#define DV_ 1024

#define BM 128
#define BN 128
#define BK 16

// ---------------------------------------------------------------------------
// GEMM NT: C[m,n] = scale * sum_k A[m,k] * B[n,k]
// A: M x K row-major, B: N x K row-major, batched over blockIdx.z
// ---------------------------------------------------------------------------
__global__ __launch_bounds__(256) void gemm_nt_kernel(
    const float* __restrict__ A, const float* __restrict__ Bm,
    float* __restrict__ C, int M, int N, int K, float scale)
{
    int b = blockIdx.z;
    A  += (size_t)b * M * K;
    Bm += (size_t)b * N * K;
    C  += (size_t)b * M * N;

    int m0 = blockIdx.y * BM;
    int n0 = blockIdx.x * BN;

    __shared__ float As[BK][BM];
    __shared__ float Bs[BK][BN];

    int tid = threadIdx.x;
    int ty = tid >> 4;   // 0..15
    int tx = tid & 15;   // 0..15

    float acc[8][8];
#pragma unroll
    for (int i = 0; i < 8; i++)
#pragma unroll
        for (int j = 0; j < 8; j++) acc[i][j] = 0.f;

    for (int k0 = 0; k0 < K; k0 += BK) {
        // Load 128x16 tiles of A and B (512 float4 each; 2 per thread)
#pragma unroll
        for (int t = 0; t < 2; t++) {
            int idx = tid + t * 256;
            int row = idx >> 2;     // 0..127
            int c4  = idx & 3;      // 0..3  (float4 within 16-col tile)
            float4 va = *(const float4*)(A  + (size_t)(m0 + row) * K + k0 + c4 * 4);
            As[c4 * 4 + 0][row] = va.x;
            As[c4 * 4 + 1][row] = va.y;
            As[c4 * 4 + 2][row] = va.z;
            As[c4 * 4 + 3][row] = va.w;
            float4 vb = *(const float4*)(Bm + (size_t)(n0 + row) * K + k0 + c4 * 4);
            Bs[c4 * 4 + 0][row] = vb.x;
            Bs[c4 * 4 + 1][row] = vb.y;
            Bs[c4 * 4 + 2][row] = vb.z;
            Bs[c4 * 4 + 3][row] = vb.w;
        }
        __syncthreads();

#pragma unroll
        for (int k = 0; k < BK; k++) {
            float ar[8], br[8];
#pragma unroll
            for (int i = 0; i < 8; i++) ar[i] = As[k][ty * 8 + i];
#pragma unroll
            for (int j = 0; j < 8; j++) br[j] = Bs[k][tx * 8 + j];
#pragma unroll
            for (int i = 0; i < 8; i++)
#pragma unroll
                for (int j = 0; j < 8; j++)
                    acc[i][j] = fmaf(ar[i], br[j], acc[i][j]);
        }
        __syncthreads();
    }

#pragma unroll
    for (int i = 0; i < 8; i++) {
        int m = m0 + ty * 8 + i;
#pragma unroll
        for (int j = 0; j < 8; j++) {
            int n = n0 + tx * 8 + j;
            C[(size_t)m * N + n] = acc[i][j] * scale;
        }
    }
}

// ---------------------------------------------------------------------------
// GEMM NN: C[m,n] = sum_k A[m,k] * B[k,n]
// A: M x K row-major, B: K x N row-major, batched over blockIdx.z
// ---------------------------------------------------------------------------
__global__ __launch_bounds__(256) void gemm_nn_kernel(
    const float* __restrict__ A, const float* __restrict__ Bm,
    float* __restrict__ C, int M, int N, int K)
{
    int b = blockIdx.z;
    A  += (size_t)b * M * K;
    Bm += (size_t)b * K * N;
    C  += (size_t)b * M * N;

    int m0 = blockIdx.y * BM;
    int n0 = blockIdx.x * BN;

    __shared__ float As[BK][BM];
    __shared__ float Bs[BK][BN];

    int tid = threadIdx.x;
    int ty = tid >> 4;
    int tx = tid & 15;

    float acc[8][8];
#pragma unroll
    for (int i = 0; i < 8; i++)
#pragma unroll
        for (int j = 0; j < 8; j++) acc[i][j] = 0.f;

    for (int k0 = 0; k0 < K; k0 += BK) {
        // A tile: 128 rows x 16 cols
#pragma unroll
        for (int t = 0; t < 2; t++) {
            int idx = tid + t * 256;
            int row = idx >> 2;
            int c4  = idx & 3;
            float4 va = *(const float4*)(A + (size_t)(m0 + row) * K + k0 + c4 * 4);
            As[c4 * 4 + 0][row] = va.x;
            As[c4 * 4 + 1][row] = va.y;
            As[c4 * 4 + 2][row] = va.z;
            As[c4 * 4 + 3][row] = va.w;
        }
        // B tile: 16 rows x 128 cols (natural layout)
#pragma unroll
        for (int t = 0; t < 2; t++) {
            int idx = tid + t * 256;
            int row = idx >> 5;      // 0..15
            int c4  = idx & 31;      // 0..31
            float4 vb = *(const float4*)(Bm + (size_t)(k0 + row) * N + n0 + c4 * 4);
            *(float4*)&Bs[row][c4 * 4] = vb;
        }
        __syncthreads();

#pragma unroll
        for (int k = 0; k < BK; k++) {
            float ar[8], br[8];
#pragma unroll
            for (int i = 0; i < 8; i++) ar[i] = As[k][ty * 8 + i];
#pragma unroll
            for (int j = 0; j < 8; j++) br[j] = Bs[k][tx * 8 + j];
#pragma unroll
            for (int i = 0; i < 8; i++)
#pragma unroll
                for (int j = 0; j < 8; j++)
                    acc[i][j] = fmaf(ar[i], br[j], acc[i][j]);
        }
        __syncthreads();
    }

#pragma unroll
    for (int i = 0; i < 8; i++) {
        int m = m0 + ty * 8 + i;
#pragma unroll
        for (int j = 0; j < 8; j++) {
            int n = n0 + tx * 8 + j;
            C[(size_t)m * N + n] = acc[i][j];
        }
    }
}

// ---------------------------------------------------------------------------
// Masked softmax over rows of W (in-place). One block per (q, b) row.
// valid = (q < qlen) ? min(klen, q+1) : 0   (causal + length masks)
// Masked entries (and fully-masked rows) become exactly 0.
// ---------------------------------------------------------------------------
__global__ __launch_bounds__(256) void softmax_kernel(
    float* __restrict__ W, const int* __restrict__ qlens,
    const int* __restrict__ klens)
{
    int q = blockIdx.x;
    int b = blockIdx.y;
    float* row = W + ((size_t)b * SQ_ + q) * SK_;

    int qlen = qlens[b];
    int klen = klens[b];
    int valid = (q < qlen) ? min(klen, q + 1) : 0;

    int tid = threadIdx.x;
    float vals[8];
    float mx = -INFINITY;
#pragma unroll
    for (int i = 0; i < 8; i++) {
        int j = tid + i * 256;
        vals[i] = row[j];
        if (j < valid) mx = fmaxf(mx, vals[i]);
    }

    __shared__ float red[256];
    red[tid] = mx;
    __syncthreads();
#pragma unroll
    for (int s = 128; s > 0; s >>= 1) {
        if (tid < s) red[tid] = fmaxf(red[tid], red[tid + s]);
        __syncthreads();
    }
    mx = red[0];
    __syncthreads();

    float sum = 0.f;
#pragma unroll
    for (int i = 0; i < 8; i++) {
        int j = tid + i * 256;
        float e = (j < valid) ? expf(vals[i] - mx) : 0.f;
        vals[i] = e;
        sum += e;
    }
    red[tid] = sum;
    __syncthreads();
#pragma unroll
    for (int s = 128; s > 0; s >>= 1) {
        if (tid < s) red[tid] += red[tid + s];
        __syncthreads();
    }
    float denom = red[0];
    float inv = (denom > 0.f) ? (1.f / denom) : 0.f;

#pragma unroll
    for (int i = 0; i < 8; i++) {
        int j = tid + i * 256;
        row[j] = vals[i] * inv;
    }
}

// ---------------------------------------------------------------------------
extern "C" void kernel_launch(void* const* d_in, const int* in_sizes, int n_in,
                              void* d_out, int out_size)
{
    const float* Q  = (const float*)d_in[0];
    const float* Kk = (const float*)d_in[1];
    const float* V  = (const float*)d_in[2];
    const int* qlens = (const int*)d_in[3];
    const int* klens = (const int*)d_in[4];

    float* ctx = (float*)d_out;                                   // (B, SQ, DV)
    float* W   = (float*)d_out + (size_t)B_ * SQ_ * DV_;          // (B, SQ, SK)

    const float scale = 1.0f / 32.0f;   // 1/sqrt(1024)

    // S = Q K^T * scale  -> into weights region
    dim3 g1(SK_ / BN, SQ_ / BM, B_);
    gemm_nt_kernel<<<g1, 256>>>(Q, Kk, W, SQ_, SK_, D_, scale);

    // masked softmax in-place
    dim3 g2(SQ_, B_);
    softmax_kernel<<<g2, 256>>>(W, qlens, klens);

    // context = W V
    dim3 g3(DV_ / BN, SQ_ / BM, B_);
    gemm_nn_kernel<<<g3, 256>>>(W, V, ctx, SQ_, DV_, SK_);
}

// round 4
// speedup vs baseline: 6.4609x; 6.4609x over previous
#include <cuda_runtime.h>
#include <cuda_bf16.h>
#include <math.h>
#include <stdint.h>

// Problem constants
#define B_  8
#define SQ_ 2048
#define SK_ 2048
#define D_  1024
#define DV_ 1024

// Split-K: each fp32 value becomes 3 bf16 slots.
// A-side [hi, hi, lo] x B-side [hi, lo, hi] => ah*bh + ah*bl + al*bh
#define K1S (3 * D_)    // 3072
#define K2S (3 * SK_)   // 6144

// ---------------------------------------------------------------------------
// Static scratch (no runtime allocation)
// ---------------------------------------------------------------------------
__device__ __align__(256) __nv_bfloat16 g_Qs[(size_t)B_ * SQ_ * K1S];
__device__ __align__(256) __nv_bfloat16 g_Ks[(size_t)B_ * SK_ * K1S];
__device__ __align__(256) __nv_bfloat16 g_Vt[(size_t)B_ * DV_ * K2S];
__device__ __align__(256) __nv_bfloat16 g_Ws[(size_t)B_ * SQ_ * K2S];

// ---------------------------------------------------------------------------
// helpers
// ---------------------------------------------------------------------------
__device__ __forceinline__ uint32_t smem_u32(const void* p) {
    uint32_t a;
    asm("{ .reg .u64 t; cvta.to.shared.u64 t, %1; cvt.u32.u64 %0, t; }"
        : "=r"(a) : "l"(p));
    return a;
}

#define SW128(o) ((o) ^ (((o) >> 3) & 0x70))

__device__ __forceinline__ void cp_async16(uint32_t dst, const void* src) {
    asm volatile("cp.async.cg.shared.global [%0], [%1], 16;"
                 :: "r"(dst), "l"(src) : "memory");
}
__device__ __forceinline__ void cp_commit() {
    asm volatile("cp.async.commit_group;" ::: "memory");
}
template <int N>
__device__ __forceinline__ void cp_wait() {
    asm volatile("cp.async.wait_group %0;" :: "n"(N) : "memory");
}

__device__ __forceinline__ void ldm_x4(uint32_t* r, uint32_t a) {
    asm volatile("ldmatrix.sync.aligned.m8n8.x4.shared.b16 {%0,%1,%2,%3}, [%4];"
                 : "=r"(r[0]), "=r"(r[1]), "=r"(r[2]), "=r"(r[3]) : "r"(a));
}

__device__ __forceinline__ void mma16816(float* d, const uint32_t* a, const uint32_t* b) {
    asm volatile(
        "mma.sync.aligned.m16n8k16.row.col.f32.bf16.bf16.f32 "
        "{%0,%1,%2,%3}, {%4,%5,%6,%7}, {%8,%9}, {%0,%1,%2,%3};"
        : "+f"(d[0]), "+f"(d[1]), "+f"(d[2]), "+f"(d[3])
        : "r"(a[0]), "r"(a[1]), "r"(a[2]), "r"(a[3]), "r"(b[0]), "r"(b[1]));
}

__device__ __forceinline__ void split_hl(float x, __nv_bfloat16& h, __nv_bfloat16& l) {
    h = __float2bfloat16(x);
    l = __float2bfloat16(x - __bfloat162float(h));
}

// ---------------------------------------------------------------------------
// Conversion: fp32 -> 3-slot bf16 split (pat 0 = [h,h,l], 1 = [h,l,h])
// ---------------------------------------------------------------------------
__global__ __launch_bounds__(256) void conv_split_kernel(
    const float* __restrict__ src, __nv_bfloat16* __restrict__ dst,
    int n, float scale, int pat)
{
    int i = blockIdx.x * 256 + threadIdx.x;
    if (i >= n) return;
    float x = src[i] * scale;
    __nv_bfloat16 h, l;
    split_hl(x, h, l);
    size_t o = (size_t)i * 3;
    if (pat == 0) { dst[o] = h; dst[o + 1] = h; dst[o + 2] = l; }
    else          { dst[o] = h; dst[o + 1] = l; dst[o + 2] = h; }
}

// ---------------------------------------------------------------------------
// V transpose + split:  V[b, k, n] -> Vt[b, n, 3k + {h,l,h}]
// ---------------------------------------------------------------------------
__global__ __launch_bounds__(256) void conv_vt_kernel(
    const float* __restrict__ V, __nv_bfloat16* __restrict__ Vt)
{
    __shared__ float tile[32][33];
    int b  = blockIdx.z;
    int k0 = blockIdx.y * 32;
    int n0 = blockIdx.x * 32;
    int tx = threadIdx.x & 31;
    int ty = threadIdx.x >> 5;

    const float* Vb = V + (size_t)b * SK_ * DV_;
#pragma unroll
    for (int p = 0; p < 4; p++) {
        int r = ty + p * 8;
        tile[r][tx] = Vb[(size_t)(k0 + r) * DV_ + n0 + tx];
    }
    __syncthreads();

    __nv_bfloat16* Vtb = Vt + (size_t)b * DV_ * K2S;
#pragma unroll
    for (int p = 0; p < 4; p++) {
        int r = ty + p * 8;
        float x = tile[tx][r];
        __nv_bfloat16 h, l;
        split_hl(x, h, l);
        size_t o = (size_t)(n0 + r) * K2S + 3 * (size_t)(k0 + tx);
        Vtb[o] = h; Vtb[o + 1] = l; Vtb[o + 2] = h;
    }
}

// ---------------------------------------------------------------------------
// Masked softmax (in-place fp32) + split bf16 [h,h,l]
// ---------------------------------------------------------------------------
__global__ __launch_bounds__(256) void softmax_split_kernel(
    float* __restrict__ W, __nv_bfloat16* __restrict__ Ws,
    const int* __restrict__ qlens, const int* __restrict__ klens)
{
    int q = blockIdx.x;
    int b = blockIdx.y;
    float* row = W + ((size_t)b * SQ_ + q) * SK_;
    __nv_bfloat16* wsrow = Ws + ((size_t)b * SQ_ + q) * K2S;

    int qlen = qlens[b];
    int klen = klens[b];
    int valid = (q < qlen) ? min(klen, q + 1) : 0;

    int tid = threadIdx.x;
    float vals[8];
    float mx = -INFINITY;
#pragma unroll
    for (int i = 0; i < 8; i++) {
        int j = tid + i * 256;
        vals[i] = row[j];
        if (j < valid) mx = fmaxf(mx, vals[i]);
    }

    __shared__ float red[256];
    red[tid] = mx;
    __syncthreads();
#pragma unroll
    for (int s = 128; s > 0; s >>= 1) {
        if (tid < s) red[tid] = fmaxf(red[tid], red[tid + s]);
        __syncthreads();
    }
    mx = red[0];
    __syncthreads();

    float sum = 0.f;
#pragma unroll
    for (int i = 0; i < 8; i++) {
        int j = tid + i * 256;
        float e = (j < valid) ? expf(vals[i] - mx) : 0.f;
        vals[i] = e;
        sum += e;
    }
    red[tid] = sum;
    __syncthreads();
#pragma unroll
    for (int s = 128; s > 0; s >>= 1) {
        if (tid < s) red[tid] += red[tid + s];
        __syncthreads();
    }
    float denom = red[0];
    float inv = (denom > 0.f) ? (1.f / denom) : 0.f;

#pragma unroll
    for (int i = 0; i < 8; i++) {
        int j = tid + i * 256;
        float wv = vals[i] * inv;
        row[j] = wv;
        __nv_bfloat16 h, l;
        split_hl(wv, h, l);
        size_t o = (size_t)3 * j;
        wsrow[o] = h; wsrow[o + 1] = h; wsrow[o + 2] = l;
    }
}

// ---------------------------------------------------------------------------
// HMMA NT GEMM: C[m,n] = sum_k A[m,k]*B[n,k]
// CTA 128x128, warp 64x32, K-chunk 64, double-buffered cp.async, SW128 smem.
// mode 0: scores  — skip tiles fully masked (softmax zero-fills them)
// mode 1: context — bound K-loop at 3*min(klen, m0+128); zero-fill if m0>=qlen
// ---------------------------------------------------------------------------
#define GEMM_SMEM (4 * 16384)

__global__ __launch_bounds__(256, 2) void gemm_hmma(
    const __nv_bfloat16* __restrict__ A,
    const __nv_bfloat16* __restrict__ Bm,
    float* __restrict__ C, int Kb, int ldc,
    const int* __restrict__ qlens, const int* __restrict__ klens, int mode)
{
    extern __shared__ __align__(128) char smem[];

    int b = blockIdx.z;
    int m0 = blockIdx.y * 128;
    int n0 = blockIdx.x * 128;
    int qlen = qlens[b];
    int klen = klens[b];

    int tid = threadIdx.x;
    int lane = tid & 31;
    int wid = tid >> 5;

    size_t M = (size_t)gridDim.y * 128;
    size_t N = (size_t)gridDim.x * 128;
    A  += (size_t)b * M * Kb + (size_t)m0 * Kb;
    Bm += (size_t)b * N * Kb + (size_t)n0 * Kb;
    C  += (size_t)b * M * ldc + (size_t)m0 * ldc + n0;

    int nch = Kb >> 6;
    int kmax = min(klen, m0 + 128);
    if (mode == 0) {
        if (m0 >= qlen || n0 >= kmax) return;   // softmax zero-fills these
    } else {
        if (m0 >= qlen) {
            // all W rows zero -> context rows zero
            for (int i = tid; i < 4096; i += 256) {
                int r = i >> 5, c4 = i & 31;
                *(float4*)(C + (size_t)r * ldc + c4 * 4) = make_float4(0.f, 0.f, 0.f, 0.f);
            }
            return;
        }
        int need = (3 * kmax + 63) >> 6;        // weights beyond kmax are exact 0
        nch = min(nch, need);
    }

    uint32_t sb = smem_u32(smem);

    // ldmatrix per-thread address components
    int warp_m = (wid >> 2) * 64;
    int warp_n = (wid & 3) * 32;
    int a_row = warp_m + (lane & 15);
    int a_cb  = (lane >> 4) * 16;
    int b_row = warp_n + (lane & 7) + ((lane >> 4) & 1) * 8;
    int b_cb  = ((lane >> 3) & 1) * 16;

    float acc[4][4][4];
#pragma unroll
    for (int mi = 0; mi < 4; mi++)
#pragma unroll
        for (int ni = 0; ni < 4; ni++)
#pragma unroll
            for (int r = 0; r < 4; r++) acc[mi][ni][r] = 0.f;

    // tile loader: A + B, 4 cp.async each per thread
    auto load_tile = [&](int s, int c) {
        uint32_t abase = sb + s * 16384;
        uint32_t bbase = sb + 32768 + s * 16384;
        const __nv_bfloat16* Ac = A + c * 64;
        const __nv_bfloat16* Bc = Bm + c * 64;
#pragma unroll
        for (int i = 0; i < 4; i++) {
            int u = tid + i * 256;
            int row = u >> 3, c8 = u & 7;
            uint32_t off = SW128((uint32_t)(row * 128 + c8 * 16));
            cp_async16(abase + off, Ac + (size_t)row * Kb + c8 * 8);
            cp_async16(bbase + off, Bc + (size_t)row * Kb + c8 * 8);
        }
    };

    load_tile(0, 0);
    cp_commit();

    for (int c = 0; c < nch; c++) {
        if (c + 1 < nch) {
            load_tile((c + 1) & 1, c + 1);
            cp_commit();
            cp_wait<1>();
        } else {
            cp_wait<0>();
        }
        __syncthreads();

        uint32_t abase = sb + (c & 1) * 16384;
        uint32_t bbase = sb + 32768 + (c & 1) * 16384;

#pragma unroll
        for (int ks = 0; ks < 4; ks++) {
            uint32_t af[4][4], bf[2][4];
#pragma unroll
            for (int mi = 0; mi < 4; mi++) {
                uint32_t o = (uint32_t)((a_row + mi * 16) * 128 + ks * 32 + a_cb);
                ldm_x4(af[mi], abase + SW128(o));
            }
#pragma unroll
            for (int nj = 0; nj < 2; nj++) {
                uint32_t o = (uint32_t)((b_row + nj * 16) * 128 + ks * 32 + b_cb);
                ldm_x4(bf[nj], bbase + SW128(o));
            }
#pragma unroll
            for (int mi = 0; mi < 4; mi++)
#pragma unroll
                for (int ni = 0; ni < 4; ni++)
                    mma16816(acc[mi][ni], af[mi], &bf[ni >> 1][(ni & 1) * 2]);
        }
        __syncthreads();
    }

    // epilogue: direct STG.64
#pragma unroll
    for (int mi = 0; mi < 4; mi++) {
        int r0 = warp_m + mi * 16 + (lane >> 2);
#pragma unroll
        for (int ni = 0; ni < 4; ni++) {
            int cc = warp_n + ni * 8 + (lane & 3) * 2;
            *(float2*)(C + (size_t)r0 * ldc + cc) =
                make_float2(acc[mi][ni][0], acc[mi][ni][1]);
            *(float2*)(C + (size_t)(r0 + 8) * ldc + cc) =
                make_float2(acc[mi][ni][2], acc[mi][ni][3]);
        }
    }
}

// ---------------------------------------------------------------------------
extern "C" void kernel_launch(void* const* d_in, const int* in_sizes, int n_in,
                              void* d_out, int out_size)
{
    const float* Q  = (const float*)d_in[0];
    const float* Kk = (const float*)d_in[1];
    const float* V  = (const float*)d_in[2];
    const int* qlens = (const int*)d_in[3];
    const int* klens = (const int*)d_in[4];

    float* ctx = (float*)d_out;                              // (B, SQ, DV)
    float* W   = (float*)d_out + (size_t)B_ * SQ_ * DV_;     // (B, SQ, SK)

    void *pQs, *pKs, *pVt, *pWs;
    cudaGetSymbolAddress(&pQs, g_Qs);
    cudaGetSymbolAddress(&pKs, g_Ks);
    cudaGetSymbolAddress(&pVt, g_Vt);
    cudaGetSymbolAddress(&pWs, g_Ws);
    cudaFuncSetAttribute(gemm_hmma,
                         cudaFuncAttributeMaxDynamicSharedMemorySize, GEMM_SMEM);

    const int nQK = B_ * SQ_ * D_;   // 16,777,216
    conv_split_kernel<<<nQK / 256, 256>>>(Q, (__nv_bfloat16*)pQs, nQK, 0.03125f, 0);
    conv_split_kernel<<<nQK / 256, 256>>>(Kk, (__nv_bfloat16*)pKs, nQK, 1.0f, 1);
    dim3 gv(DV_ / 32, SK_ / 32, B_);
    conv_vt_kernel<<<gv, 256>>>(V, (__nv_bfloat16*)pVt);

    // S = Q K^T (scale folded into Q) -> weights region (fp32)
    dim3 g1(SK_ / 128, SQ_ / 128, B_);
    gemm_hmma<<<g1, 256, GEMM_SMEM>>>(
        (const __nv_bfloat16*)pQs, (const __nv_bfloat16*)pKs, W, K1S, SK_,
        qlens, klens, 0);

    // masked softmax + split bf16 weights
    dim3 gs(SQ_, B_);
    softmax_split_kernel<<<gs, 256>>>(W, (__nv_bfloat16*)pWs, qlens, klens);

    // context = W V (via Vt, NT form)
    dim3 g2(DV_ / 128, SQ_ / 128, B_);
    gemm_hmma<<<g2, 256, GEMM_SMEM>>>(
        (const __nv_bfloat16*)pWs, (const __nv_bfloat16*)pVt, ctx, K2S, DV_,
        qlens, klens, 1);
}

// round 5
// speedup vs baseline: 8.0647x; 1.2482x over previous
#include <cuda_runtime.h>
#include <cuda_bf16.h>
#include <math.h>
#include <stdint.h>

// Problem constants
#define B_  8
#define SQ_ 2048
#define SK_ 2048
#define D_  1024
#define DV_ 1024

// Split-K: each fp32 value becomes 3 bf16 slots.
// A-side [hi, hi, lo] x B-side [hi, lo, hi] => ah*bh + ah*bl + al*bh
#define K1S (3 * D_)    // 3072
#define K2S (3 * SK_)   // 6144

// ---------------------------------------------------------------------------
// Static scratch
// ---------------------------------------------------------------------------
__device__ __align__(256) __nv_bfloat16 g_Qs[(size_t)B_ * SQ_ * K1S];
__device__ __align__(256) __nv_bfloat16 g_Ks[(size_t)B_ * SK_ * K1S];
__device__ __align__(256) __nv_bfloat16 g_Vt[(size_t)B_ * DV_ * K2S];
__device__ __align__(256) __nv_bfloat16 g_Ws[(size_t)B_ * SQ_ * K2S];

// ---------------------------------------------------------------------------
// helpers
// ---------------------------------------------------------------------------
__device__ __forceinline__ uint32_t smem_u32(const void* p) {
    uint32_t a;
    asm("{ .reg .u64 t; cvta.to.shared.u64 t, %1; cvt.u32.u64 %0, t; }"
        : "=r"(a) : "l"(p));
    return a;
}

#define SW128(o) ((o) ^ (((o) >> 3) & 0x70))

__device__ __forceinline__ void cp_async16(uint32_t dst, const void* src) {
    asm volatile("cp.async.cg.shared.global [%0], [%1], 16;"
                 :: "r"(dst), "l"(src) : "memory");
}
__device__ __forceinline__ void cp_commit() {
    asm volatile("cp.async.commit_group;" ::: "memory");
}
template <int N>
__device__ __forceinline__ void cp_wait() {
    asm volatile("cp.async.wait_group %0;" :: "n"(N) : "memory");
}

__device__ __forceinline__ void ldm_x4(uint32_t* r, uint32_t a) {
    asm volatile("ldmatrix.sync.aligned.m8n8.x4.shared.b16 {%0,%1,%2,%3}, [%4];"
                 : "=r"(r[0]), "=r"(r[1]), "=r"(r[2]), "=r"(r[3]) : "r"(a));
}

__device__ __forceinline__ void mma16816(float* d, const uint32_t* a, const uint32_t* b) {
    asm volatile(
        "mma.sync.aligned.m16n8k16.row.col.f32.bf16.bf16.f32 "
        "{%0,%1,%2,%3}, {%4,%5,%6,%7}, {%8,%9}, {%0,%1,%2,%3};"
        : "+f"(d[0]), "+f"(d[1]), "+f"(d[2]), "+f"(d[3])
        : "r"(a[0]), "r"(a[1]), "r"(a[2]), "r"(a[3]), "r"(b[0]), "r"(b[1]));
}

__device__ __forceinline__ void split_hl(float x, unsigned short& hb, unsigned short& lb) {
    __nv_bfloat16 h = __float2bfloat16(x);
    __nv_bfloat16 l = __float2bfloat16(x - __bfloat162float(h));
    hb = __bfloat16_as_ushort(h);
    lb = __bfloat16_as_ushort(l);
}

// Pack 8 fp32 values into 24 bf16 slots (3x uint4).
// pat 0: per value [h,h,l]   (A-side)
// pat 1: per value [h,l,h]   (B-side)
__device__ __forceinline__ void pack8(const float* v, uint4* out, int pat) {
    unsigned short s[24];
#pragma unroll
    for (int i = 0; i < 8; i++) {
        unsigned short hb, lb;
        split_hl(v[i], hb, lb);
        if (pat == 0) { s[3*i] = hb; s[3*i+1] = hb; s[3*i+2] = lb; }
        else          { s[3*i] = hb; s[3*i+1] = lb; s[3*i+2] = hb; }
    }
    uint32_t u[12];
#pragma unroll
    for (int j = 0; j < 12; j++)
        u[j] = (uint32_t)s[2*j] | ((uint32_t)s[2*j+1] << 16);
    out[0] = make_uint4(u[0], u[1], u[2], u[3]);
    out[1] = make_uint4(u[4], u[5], u[6], u[7]);
    out[2] = make_uint4(u[8], u[9], u[10], u[11]);
}

// ---------------------------------------------------------------------------
// fp32 -> 3-slot bf16 split, 8 values/thread, fully vectorized
// ---------------------------------------------------------------------------
__global__ __launch_bounds__(256) void conv_split8_kernel(
    const float* __restrict__ src, __nv_bfloat16* __restrict__ dst,
    int n8, float scale, int pat)
{
    int i = blockIdx.x * 256 + threadIdx.x;
    if (i >= n8) return;
    float4 a = ((const float4*)src)[2*i];
    float4 b = ((const float4*)src)[2*i+1];
    float v[8] = {a.x*scale, a.y*scale, a.z*scale, a.w*scale,
                  b.x*scale, b.y*scale, b.z*scale, b.w*scale};
    uint4 o[3];
    pack8(v, o, pat);
    uint4* d = (uint4*)(dst + (size_t)i * 24);
    d[0] = o[0]; d[1] = o[1]; d[2] = o[2];
}

// ---------------------------------------------------------------------------
// V transpose + split: V[b,k,n] -> Vt[b,n,3k+{h,l,h}], vectorized stores
// tile = 64(k) x 32(n)
// ---------------------------------------------------------------------------
__global__ __launch_bounds__(256) void conv_vt_kernel(
    const float* __restrict__ V, __nv_bfloat16* __restrict__ Vt)
{
    __shared__ float tile[64][33];
    int b  = blockIdx.z;
    int k0 = blockIdx.y * 64;
    int n0 = blockIdx.x * 32;
    int tid = threadIdx.x;

    const float* Vb = V + (size_t)b * SK_ * DV_;
    int c = tid & 31;
    int r0 = tid >> 5;
#pragma unroll
    for (int p = 0; p < 8; p++) {
        int r = r0 + p * 8;
        tile[r][c] = Vb[(size_t)(k0 + r) * DV_ + n0 + c];
    }
    __syncthreads();

    int n  = tid >> 3;     // 0..31
    int kg = tid & 7;      // 0..7 (8 k each)
    float v[8];
#pragma unroll
    for (int i = 0; i < 8; i++) v[i] = tile[kg * 8 + i][n];
    uint4 o[3];
    pack8(v, o, 1);
    __nv_bfloat16* row = Vt + (size_t)b * DV_ * K2S
                       + (size_t)(n0 + n) * K2S + 3 * (k0 + kg * 8);
    uint4* d = (uint4*)row;
    d[0] = o[0]; d[1] = o[1]; d[2] = o[2];
}

// ---------------------------------------------------------------------------
// Masked softmax (fp32 W in-place) + split bf16 Ws ([h,h,l]); vectorized,
// Ws writes limited to what GEMM2 actually reads.
// ---------------------------------------------------------------------------
__global__ __launch_bounds__(256) void softmax_split_kernel(
    float* __restrict__ W, __nv_bfloat16* __restrict__ Ws,
    const int* __restrict__ qlens, const int* __restrict__ klens)
{
    int q = blockIdx.x;
    int b = blockIdx.y;
    float* row = W + ((size_t)b * SQ_ + q) * SK_;

    int qlen = qlens[b];
    int klen = klens[b];
    int valid = (q < qlen) ? min(klen, q + 1) : 0;

    int tid = threadIdx.x;
    int j0 = tid * 8;
    float4 x0 = ((const float4*)row)[2*tid];
    float4 x1 = ((const float4*)row)[2*tid+1];
    float v[8] = {x0.x, x0.y, x0.z, x0.w, x1.x, x1.y, x1.z, x1.w};

    float mx = -INFINITY;
#pragma unroll
    for (int i = 0; i < 8; i++)
        if (j0 + i < valid) mx = fmaxf(mx, v[i]);

    __shared__ float red[256];
    red[tid] = mx;
    __syncthreads();
#pragma unroll
    for (int s = 128; s > 0; s >>= 1) {
        if (tid < s) red[tid] = fmaxf(red[tid], red[tid + s]);
        __syncthreads();
    }
    mx = red[0];
    __syncthreads();

    float sum = 0.f;
#pragma unroll
    for (int i = 0; i < 8; i++) {
        float e = (j0 + i < valid) ? expf(v[i] - mx) : 0.f;
        v[i] = e;
        sum += e;
    }
    red[tid] = sum;
    __syncthreads();
#pragma unroll
    for (int s = 128; s > 0; s >>= 1) {
        if (tid < s) red[tid] += red[tid + s];
        __syncthreads();
    }
    float denom = red[0];
    float inv = (denom > 0.f) ? (1.f / denom) : 0.f;

#pragma unroll
    for (int i = 0; i < 8; i++) v[i] *= inv;

    ((float4*)row)[2*tid]   = make_float4(v[0], v[1], v[2], v[3]);
    ((float4*)row)[2*tid+1] = make_float4(v[4], v[5], v[6], v[7]);

    // GEMM2 reads Ws slots < 3*kmax_tile + 64 => values < kmax_tile + 22
    int kmaxt = min(klen, ((q >> 7) + 1) << 7);
    if (j0 < min(SK_, kmaxt + 22)) {
        uint4 o[3];
        pack8(v, o, 0);
        __nv_bfloat16* wsrow = Ws + ((size_t)b * SQ_ + q) * K2S + 3 * j0;
        uint4* d = (uint4*)wsrow;
        d[0] = o[0]; d[1] = o[1]; d[2] = o[2];
    }
}

// ---------------------------------------------------------------------------
// HMMA NT GEMM: C[m,n] = sum_k A[m,k]*B[n,k]
// CTA 128x128, warp 64x32, K-chunk 64, 3-stage cp.async pipeline (one sync
// per chunk), SW128 smem.
// mode 0: scores  — triangular 1D grid (n_tile <= m_tile), skip masked tiles
// mode 1: context — bound K-loop at 3*min(klen, m0+128); zero-fill if m0>=qlen
// ---------------------------------------------------------------------------
#define STAGES 3
#define STAGE_BYTES 32768
#define GEMM_SMEM (STAGES * STAGE_BYTES)

__global__ __launch_bounds__(256, 2) void gemm_hmma(
    const __nv_bfloat16* __restrict__ A,
    const __nv_bfloat16* __restrict__ Bm,
    float* __restrict__ C, int Kb, int ldc, int M, int N,
    const int* __restrict__ qlens, const int* __restrict__ klens, int mode)
{
    extern __shared__ __align__(1024) char smem[];

    int b = blockIdx.z;
    int m0, n0;
    if (mode == 0) {
        // triangular decode: i -> (mt, nt) with nt <= mt
        int i = blockIdx.x;
        int mt = (int)((sqrtf(8.0f * i + 1.0f) - 1.0f) * 0.5f);
        while ((mt + 1) * (mt + 2) / 2 <= i) mt++;
        while (mt * (mt + 1) / 2 > i) mt--;
        int nt = i - mt * (mt + 1) / 2;
        m0 = mt * 128; n0 = nt * 128;
    } else {
        m0 = blockIdx.y * 128;
        n0 = blockIdx.x * 128;
    }
    int qlen = qlens[b];
    int klen = klens[b];

    int tid = threadIdx.x;
    int lane = tid & 31;
    int wid = tid >> 5;

    A  += (size_t)b * M * Kb + (size_t)m0 * Kb;
    Bm += (size_t)b * N * Kb + (size_t)n0 * Kb;
    C  += (size_t)b * M * ldc + (size_t)m0 * ldc + n0;

    int nch = Kb >> 6;
    int kmax = min(klen, m0 + 128);
    if (mode == 0) {
        if (m0 >= qlen || n0 >= kmax) return;   // softmax zero-fills these
    } else {
        if (m0 >= qlen) {
            for (int i = tid; i < 4096; i += 256) {
                int r = i >> 5, c4 = i & 31;
                *(float4*)(C + (size_t)r * ldc + c4 * 4) = make_float4(0.f, 0.f, 0.f, 0.f);
            }
            return;
        }
        int need = (3 * kmax + 63) >> 6;
        nch = min(nch, need);
    }

    uint32_t sb = smem_u32(smem);

    int warp_m = (wid >> 2) * 64;
    int warp_n = (wid & 3) * 32;
    int a_row = warp_m + (lane & 15);
    int a_cb  = (lane >> 4) * 16;
    int b_row = warp_n + (lane & 7) + ((lane >> 4) & 1) * 8;
    int b_cb  = ((lane >> 3) & 1) * 16;

    float acc[4][4][4];
#pragma unroll
    for (int mi = 0; mi < 4; mi++)
#pragma unroll
        for (int ni = 0; ni < 4; ni++)
#pragma unroll
            for (int r = 0; r < 4; r++) acc[mi][ni][r] = 0.f;

    auto load_tile = [&](int s, int c) {
        uint32_t abase = sb + s * STAGE_BYTES;
        uint32_t bbase = abase + 16384;
        const __nv_bfloat16* Ac = A + c * 64;
        const __nv_bfloat16* Bc = Bm + c * 64;
#pragma unroll
        for (int i = 0; i < 4; i++) {
            int u = tid + i * 256;
            int row = u >> 3, c8 = u & 7;
            uint32_t off = SW128((uint32_t)(row * 128 + c8 * 16));
            cp_async16(abase + off, Ac + (size_t)row * Kb + c8 * 8);
            cp_async16(bbase + off, Bc + (size_t)row * Kb + c8 * 8);
        }
    };

    // prologue: stages 0,1
    load_tile(0, 0);
    cp_commit();
    if (nch > 1) { load_tile(1, 1); cp_commit(); }

    for (int c = 0; c < nch; c++) {
        if (c + 1 < nch) cp_wait<1>(); else cp_wait<0>();
        __syncthreads();   // data of chunk c visible; all warps past compute(c-1)

        if (c + 2 < nch) { load_tile((c + 2) % STAGES, c + 2); cp_commit(); }

        int s = c % STAGES;
        uint32_t abase = sb + s * STAGE_BYTES;
        uint32_t bbase = abase + 16384;

#pragma unroll
        for (int ks = 0; ks < 4; ks++) {
            uint32_t af[4][4], bf[2][4];
#pragma unroll
            for (int mi = 0; mi < 4; mi++) {
                uint32_t o = (uint32_t)((a_row + mi * 16) * 128 + ks * 32 + a_cb);
                ldm_x4(af[mi], abase + SW128(o));
            }
#pragma unroll
            for (int nj = 0; nj < 2; nj++) {
                uint32_t o = (uint32_t)((b_row + nj * 16) * 128 + ks * 32 + b_cb);
                ldm_x4(bf[nj], bbase + SW128(o));
            }
#pragma unroll
            for (int mi = 0; mi < 4; mi++)
#pragma unroll
                for (int ni = 0; ni < 4; ni++)
                    mma16816(acc[mi][ni], af[mi], &bf[ni >> 1][(ni & 1) * 2]);
        }
    }

    // epilogue
#pragma unroll
    for (int mi = 0; mi < 4; mi++) {
        int r0 = warp_m + mi * 16 + (lane >> 2);
#pragma unroll
        for (int ni = 0; ni < 4; ni++) {
            int cc = warp_n + ni * 8 + (lane & 3) * 2;
            *(float2*)(C + (size_t)r0 * ldc + cc) =
                make_float2(acc[mi][ni][0], acc[mi][ni][1]);
            *(float2*)(C + (size_t)(r0 + 8) * ldc + cc) =
                make_float2(acc[mi][ni][2], acc[mi][ni][3]);
        }
    }
}

// ---------------------------------------------------------------------------
extern "C" void kernel_launch(void* const* d_in, const int* in_sizes, int n_in,
                              void* d_out, int out_size)
{
    const float* Q  = (const float*)d_in[0];
    const float* Kk = (const float*)d_in[1];
    const float* V  = (const float*)d_in[2];
    const int* qlens = (const int*)d_in[3];
    const int* klens = (const int*)d_in[4];

    float* ctx = (float*)d_out;                              // (B, SQ, DV)
    float* W   = (float*)d_out + (size_t)B_ * SQ_ * DV_;     // (B, SQ, SK)

    void *pQs, *pKs, *pVt, *pWs;
    cudaGetSymbolAddress(&pQs, g_Qs);
    cudaGetSymbolAddress(&pKs, g_Ks);
    cudaGetSymbolAddress(&pVt, g_Vt);
    cudaGetSymbolAddress(&pWs, g_Ws);
    cudaFuncSetAttribute(gemm_hmma,
                         cudaFuncAttributeMaxDynamicSharedMemorySize, GEMM_SMEM);

    const int n8 = B_ * SQ_ * D_ / 8;   // 2,097,152
    conv_split8_kernel<<<n8 / 256, 256>>>(Q, (__nv_bfloat16*)pQs, n8, 0.03125f, 0);
    conv_split8_kernel<<<n8 / 256, 256>>>(Kk, (__nv_bfloat16*)pKs, n8, 1.0f, 1);
    dim3 gv(DV_ / 32, SK_ / 64, B_);
    conv_vt_kernel<<<gv, 256>>>(V, (__nv_bfloat16*)pVt);

    // S = Q K^T (scale folded into Q) -> weights region (fp32), triangular grid
    dim3 g1(16 * 17 / 2, 1, B_);
    gemm_hmma<<<g1, 256, GEMM_SMEM>>>(
        (const __nv_bfloat16*)pQs, (const __nv_bfloat16*)pKs, W, K1S, SK_,
        SQ_, SK_, qlens, klens, 0);

    // masked softmax + split bf16 weights
    dim3 gs(SQ_, B_);
    softmax_split_kernel<<<gs, 256>>>(W, (__nv_bfloat16*)pWs, qlens, klens);

    // context = W V (via Vt, NT form)
    dim3 g2(DV_ / 128, SQ_ / 128, B_);
    gemm_hmma<<<g2, 256, GEMM_SMEM>>>(
        (const __nv_bfloat16*)pWs, (const __nv_bfloat16*)pVt, ctx, K2S, DV_,
        SQ_, DV_, qlens, klens, 1);
}

// round 6
// speedup vs baseline: 8.6000x; 1.0664x over previous
#include <cuda_runtime.h>
#include <cuda_bf16.h>
#include <math.h>
#include <stdint.h>

// Problem constants
#define B_  8
#define SQ_ 2048
#define SK_ 2048
#define D_  1024
#define DV_ 1024

// Split-K: each fp32 value becomes 3 bf16 slots.
// A-side [hi, hi, lo] x B-side [hi, lo, hi] => ah*bh + ah*bl + al*bh
#define K1S (3 * D_)    // 3072
#define K2S (3 * SK_)   // 6144

// ---------------------------------------------------------------------------
// Static scratch
// ---------------------------------------------------------------------------
__device__ __align__(256) __nv_bfloat16 g_Qs[(size_t)B_ * SQ_ * K1S];
__device__ __align__(256) __nv_bfloat16 g_Ks[(size_t)B_ * SK_ * K1S];
__device__ __align__(256) __nv_bfloat16 g_Vt[(size_t)B_ * DV_ * K2S];
__device__ __align__(256) __nv_bfloat16 g_Ws[(size_t)B_ * SQ_ * K2S];

// ---------------------------------------------------------------------------
// helpers
// ---------------------------------------------------------------------------
__device__ __forceinline__ uint32_t smem_u32(const void* p) {
    uint32_t a;
    asm("{ .reg .u64 t; cvta.to.shared.u64 t, %1; cvt.u32.u64 %0, t; }"
        : "=r"(a) : "l"(p));
    return a;
}

#define SW128(o) ((o) ^ (((o) >> 3) & 0x70))

__device__ __forceinline__ void cp_async16(uint32_t dst, const void* src) {
    asm volatile("cp.async.cg.shared.global [%0], [%1], 16;"
                 :: "r"(dst), "l"(src) : "memory");
}
__device__ __forceinline__ void cp_commit() {
    asm volatile("cp.async.commit_group;" ::: "memory");
}
template <int N>
__device__ __forceinline__ void cp_wait() {
    asm volatile("cp.async.wait_group %0;" :: "n"(N) : "memory");
}

__device__ __forceinline__ void ldm_x4(uint32_t* r, uint32_t a) {
    asm volatile("ldmatrix.sync.aligned.m8n8.x4.shared.b16 {%0,%1,%2,%3}, [%4];"
                 : "=r"(r[0]), "=r"(r[1]), "=r"(r[2]), "=r"(r[3]) : "r"(a));
}

__device__ __forceinline__ void mma16816(float* d, const uint32_t* a, const uint32_t* b) {
    asm volatile(
        "mma.sync.aligned.m16n8k16.row.col.f32.bf16.bf16.f32 "
        "{%0,%1,%2,%3}, {%4,%5,%6,%7}, {%8,%9}, {%0,%1,%2,%3};"
        : "+f"(d[0]), "+f"(d[1]), "+f"(d[2]), "+f"(d[3])
        : "r"(a[0]), "r"(a[1]), "r"(a[2]), "r"(a[3]), "r"(b[0]), "r"(b[1]));
}

__device__ __forceinline__ void split_hl(float x, unsigned short& hb, unsigned short& lb) {
    __nv_bfloat16 h = __float2bfloat16(x);
    __nv_bfloat16 l = __float2bfloat16(x - __bfloat162float(h));
    hb = __bfloat16_as_ushort(h);
    lb = __bfloat16_as_ushort(l);
}

// Pack 8 fp32 values into 24 bf16 slots (3x uint4).
// pat 0: per value [h,h,l]   (A-side)
// pat 1: per value [h,l,h]   (B-side)
__device__ __forceinline__ void pack8(const float* v, uint4* out, int pat) {
    unsigned short s[24];
#pragma unroll
    for (int i = 0; i < 8; i++) {
        unsigned short hb, lb;
        split_hl(v[i], hb, lb);
        if (pat == 0) { s[3*i] = hb; s[3*i+1] = hb; s[3*i+2] = lb; }
        else          { s[3*i] = hb; s[3*i+1] = lb; s[3*i+2] = hb; }
    }
    uint32_t u[12];
#pragma unroll
    for (int j = 0; j < 12; j++)
        u[j] = (uint32_t)s[2*j] | ((uint32_t)s[2*j+1] << 16);
    out[0] = make_uint4(u[0], u[1], u[2], u[3]);
    out[1] = make_uint4(u[4], u[5], u[6], u[7]);
    out[2] = make_uint4(u[8], u[9], u[10], u[11]);
}

// ---------------------------------------------------------------------------
// fp32 -> 3-slot bf16 split, 8 values/thread, fully vectorized
// ---------------------------------------------------------------------------
__global__ __launch_bounds__(256) void conv_split8_kernel(
    const float* __restrict__ src, __nv_bfloat16* __restrict__ dst,
    int n8, float scale, int pat)
{
    int i = blockIdx.x * 256 + threadIdx.x;
    if (i >= n8) return;
    float4 a = ((const float4*)src)[2*i];
    float4 b = ((const float4*)src)[2*i+1];
    float v[8] = {a.x*scale, a.y*scale, a.z*scale, a.w*scale,
                  b.x*scale, b.y*scale, b.z*scale, b.w*scale};
    uint4 o[3];
    pack8(v, o, pat);
    uint4* d = (uint4*)(dst + (size_t)i * 24);
    d[0] = o[0]; d[1] = o[1]; d[2] = o[2];
}

// ---------------------------------------------------------------------------
// V transpose + split: V[b,k,n] -> Vt[b,n,3k+{h,l,h}], vectorized stores
// ---------------------------------------------------------------------------
__global__ __launch_bounds__(256) void conv_vt_kernel(
    const float* __restrict__ V, __nv_bfloat16* __restrict__ Vt)
{
    __shared__ float tile[64][33];
    int b  = blockIdx.z;
    int k0 = blockIdx.y * 64;
    int n0 = blockIdx.x * 32;
    int tid = threadIdx.x;

    const float* Vb = V + (size_t)b * SK_ * DV_;
    int c = tid & 31;
    int r0 = tid >> 5;
#pragma unroll
    for (int p = 0; p < 8; p++) {
        int r = r0 + p * 8;
        tile[r][c] = Vb[(size_t)(k0 + r) * DV_ + n0 + c];
    }
    __syncthreads();

    int n  = tid >> 3;     // 0..31
    int kg = tid & 7;      // 0..7
    float v[8];
#pragma unroll
    for (int i = 0; i < 8; i++) v[i] = tile[kg * 8 + i][n];
    uint4 o[3];
    pack8(v, o, 1);
    __nv_bfloat16* row = Vt + (size_t)b * DV_ * K2S
                       + (size_t)(n0 + n) * K2S + 3 * (k0 + kg * 8);
    uint4* d = (uint4*)row;
    d[0] = o[0]; d[1] = o[1]; d[2] = o[2];
}

// ---------------------------------------------------------------------------
// Masked softmax (fp32 W in-place) + split bf16 Ws ([h,h,l]); vectorized,
// Ws writes limited to what GEMM2 actually reads (cols & rows).
// ---------------------------------------------------------------------------
__global__ __launch_bounds__(256) void softmax_split_kernel(
    float* __restrict__ W, __nv_bfloat16* __restrict__ Ws,
    const int* __restrict__ qlens, const int* __restrict__ klens)
{
    int q = blockIdx.x;
    int b = blockIdx.y;
    float* row = W + ((size_t)b * SQ_ + q) * SK_;

    int qlen = qlens[b];
    int klen = klens[b];
    int valid = (q < qlen) ? min(klen, q + 1) : 0;

    int tid = threadIdx.x;
    int j0 = tid * 8;
    float4 x0 = ((const float4*)row)[2*tid];
    float4 x1 = ((const float4*)row)[2*tid+1];
    float v[8] = {x0.x, x0.y, x0.z, x0.w, x1.x, x1.y, x1.z, x1.w};

    float mx = -INFINITY;
#pragma unroll
    for (int i = 0; i < 8; i++)
        if (j0 + i < valid) mx = fmaxf(mx, v[i]);

    __shared__ float red[256];
    red[tid] = mx;
    __syncthreads();
#pragma unroll
    for (int s = 128; s > 0; s >>= 1) {
        if (tid < s) red[tid] = fmaxf(red[tid], red[tid + s]);
        __syncthreads();
    }
    mx = red[0];
    __syncthreads();

    float sum = 0.f;
#pragma unroll
    for (int i = 0; i < 8; i++) {
        float e = (j0 + i < valid) ? expf(v[i] - mx) : 0.f;
        v[i] = e;
        sum += e;
    }
    red[tid] = sum;
    __syncthreads();
#pragma unroll
    for (int s = 128; s > 0; s >>= 1) {
        if (tid < s) red[tid] += red[tid + s];
        __syncthreads();
    }
    float denom = red[0];
    float inv = (denom > 0.f) ? (1.f / denom) : 0.f;

#pragma unroll
    for (int i = 0; i < 8; i++) v[i] *= inv;

    ((float4*)row)[2*tid]   = make_float4(v[0], v[1], v[2], v[3]);
    ((float4*)row)[2*tid+1] = make_float4(v[4], v[5], v[6], v[7]);

    // GEMM2 never reads rows q >= ceil128(qlen) (those tiles zero-fill/skip)
    if (q >= ((qlen + 127) & ~127)) return;
    // GEMM2 reads Ws slots < 3*kmax_tile + 64 => values < kmax_tile + 22
    int kmaxt = min(klen, ((q >> 7) + 1) << 7);
    if (j0 < min(SK_, kmaxt + 22)) {
        uint4 o[3];
        pack8(v, o, 0);
        __nv_bfloat16* wsrow = Ws + ((size_t)b * SQ_ + q) * K2S + 3 * j0;
        uint4* d = (uint4*)wsrow;
        d[0] = o[0]; d[1] = o[1]; d[2] = o[2];
    }
}

// ---------------------------------------------------------------------------
// HMMA NT GEMM: C[m,n] = sum_k A[m,k]*B[n,k]
// CTA 128x128, 4 warps, warp tile 64x64 (maximizes frag reuse -> less SMEM BW),
// K-chunk 64, 3-stage cp.async pipeline, SW128 smem.
// mode 0: scores  — triangular 1D grid (n_tile <= m_tile), skip masked tiles
// mode 1: context — bound K-loop at 3*min(klen, m0+128); zero-fill if m0>=qlen
// ---------------------------------------------------------------------------
#define STAGES 3
#define STAGE_BYTES 32768
#define GEMM_SMEM (STAGES * STAGE_BYTES)

__global__ __launch_bounds__(128, 2) void gemm_hmma(
    const __nv_bfloat16* __restrict__ A,
    const __nv_bfloat16* __restrict__ Bm,
    float* __restrict__ C, int Kb, int ldc, int M, int N,
    const int* __restrict__ qlens, const int* __restrict__ klens, int mode)
{
    extern __shared__ __align__(1024) char smem[];

    int b = blockIdx.z;
    int m0, n0;
    if (mode == 0) {
        int i = blockIdx.x;
        int mt = (int)((sqrtf(8.0f * i + 1.0f) - 1.0f) * 0.5f);
        while ((mt + 1) * (mt + 2) / 2 <= i) mt++;
        while (mt * (mt + 1) / 2 > i) mt--;
        int nt = i - mt * (mt + 1) / 2;
        m0 = mt * 128; n0 = nt * 128;
    } else {
        m0 = blockIdx.y * 128;
        n0 = blockIdx.x * 128;
    }
    int qlen = qlens[b];
    int klen = klens[b];

    int tid = threadIdx.x;
    int lane = tid & 31;
    int wid = tid >> 5;          // 0..3

    A  += (size_t)b * M * Kb + (size_t)m0 * Kb;
    Bm += (size_t)b * N * Kb + (size_t)n0 * Kb;
    C  += (size_t)b * M * ldc + (size_t)m0 * ldc + n0;

    int nch = Kb >> 6;
    int kmax = min(klen, m0 + 128);
    if (mode == 0) {
        if (m0 >= qlen || n0 >= kmax) return;
    } else {
        if (m0 >= qlen) {
            for (int i = tid; i < 4096; i += 128) {
                int r = i >> 5, c4 = i & 31;
                *(float4*)(C + (size_t)r * ldc + c4 * 4) = make_float4(0.f, 0.f, 0.f, 0.f);
            }
            return;
        }
        int need = (3 * kmax + 63) >> 6;
        nch = min(nch, need);
    }

    uint32_t sb = smem_u32(smem);

    // 2x2 warp grid, 64x64 per warp
    int warp_m = (wid >> 1) * 64;
    int warp_n = (wid & 1) * 64;
    int a_row = warp_m + (lane & 15);
    int a_cb  = (lane >> 4) * 16;
    int b_row = warp_n + (lane & 7) + ((lane >> 4) & 1) * 8;
    int b_cb  = ((lane >> 3) & 1) * 16;

    float acc[4][8][4];
#pragma unroll
    for (int mi = 0; mi < 4; mi++)
#pragma unroll
        for (int ni = 0; ni < 8; ni++)
#pragma unroll
            for (int r = 0; r < 4; r++) acc[mi][ni][r] = 0.f;

    auto load_tile = [&](int s, int c) {
        uint32_t abase = sb + s * STAGE_BYTES;
        uint32_t bbase = abase + 16384;
        const __nv_bfloat16* Ac = A + c * 64;
        const __nv_bfloat16* Bc = Bm + c * 64;
#pragma unroll
        for (int i = 0; i < 8; i++) {
            int u = tid + i * 128;
            int row = u >> 3, c8 = u & 7;
            uint32_t off = SW128((uint32_t)(row * 128 + c8 * 16));
            cp_async16(abase + off, Ac + (size_t)row * Kb + c8 * 8);
            cp_async16(bbase + off, Bc + (size_t)row * Kb + c8 * 8);
        }
    };

    load_tile(0, 0);
    cp_commit();
    if (nch > 1) { load_tile(1, 1); cp_commit(); }

    for (int c = 0; c < nch; c++) {
        if (c + 1 < nch) cp_wait<1>(); else cp_wait<0>();
        __syncthreads();

        if (c + 2 < nch) { load_tile((c + 2) % STAGES, c + 2); cp_commit(); }

        int s = c % STAGES;
        uint32_t abase = sb + s * STAGE_BYTES;
        uint32_t bbase = abase + 16384;

#pragma unroll
        for (int ks = 0; ks < 4; ks++) {
            uint32_t af[4][4], bf[4][4];
#pragma unroll
            for (int mi = 0; mi < 4; mi++) {
                uint32_t o = (uint32_t)((a_row + mi * 16) * 128 + ks * 32 + a_cb);
                ldm_x4(af[mi], abase + SW128(o));
            }
#pragma unroll
            for (int nj = 0; nj < 4; nj++) {
                uint32_t o = (uint32_t)((b_row + nj * 16) * 128 + ks * 32 + b_cb);
                ldm_x4(bf[nj], bbase + SW128(o));
            }
#pragma unroll
            for (int mi = 0; mi < 4; mi++)
#pragma unroll
                for (int ni = 0; ni < 8; ni++)
                    mma16816(acc[mi][ni], af[mi], &bf[ni >> 1][(ni & 1) * 2]);
        }
    }

    // epilogue: each warp stores its 64x64 block
#pragma unroll
    for (int mi = 0; mi < 4; mi++) {
        int r0 = warp_m + mi * 16 + (lane >> 2);
#pragma unroll
        for (int ni = 0; ni < 8; ni++) {
            int cc = warp_n + ni * 8 + (lane & 3) * 2;
            *(float2*)(C + (size_t)r0 * ldc + cc) =
                make_float2(acc[mi][ni][0], acc[mi][ni][1]);
            *(float2*)(C + (size_t)(r0 + 8) * ldc + cc) =
                make_float2(acc[mi][ni][2], acc[mi][ni][3]);
        }
    }
}

// ---------------------------------------------------------------------------
extern "C" void kernel_launch(void* const* d_in, const int* in_sizes, int n_in,
                              void* d_out, int out_size)
{
    const float* Q  = (const float*)d_in[0];
    const float* Kk = (const float*)d_in[1];
    const float* V  = (const float*)d_in[2];
    const int* qlens = (const int*)d_in[3];
    const int* klens = (const int*)d_in[4];

    float* ctx = (float*)d_out;                              // (B, SQ, DV)
    float* W   = (float*)d_out + (size_t)B_ * SQ_ * DV_;     // (B, SQ, SK)

    void *pQs, *pKs, *pVt, *pWs;
    cudaGetSymbolAddress(&pQs, g_Qs);
    cudaGetSymbolAddress(&pKs, g_Ks);
    cudaGetSymbolAddress(&pVt, g_Vt);
    cudaGetSymbolAddress(&pWs, g_Ws);
    cudaFuncSetAttribute(gemm_hmma,
                         cudaFuncAttributeMaxDynamicSharedMemorySize, GEMM_SMEM);

    const int n8 = B_ * SQ_ * D_ / 8;
    conv_split8_kernel<<<n8 / 256, 256>>>(Q, (__nv_bfloat16*)pQs, n8, 0.03125f, 0);
    conv_split8_kernel<<<n8 / 256, 256>>>(Kk, (__nv_bfloat16*)pKs, n8, 1.0f, 1);
    dim3 gv(DV_ / 32, SK_ / 64, B_);
    conv_vt_kernel<<<gv, 256>>>(V, (__nv_bfloat16*)pVt);

    // S = Q K^T (scale folded into Q) -> weights region (fp32), triangular grid
    dim3 g1(16 * 17 / 2, 1, B_);
    gemm_hmma<<<g1, 128, GEMM_SMEM>>>(
        (const __nv_bfloat16*)pQs, (const __nv_bfloat16*)pKs, W, K1S, SK_,
        SQ_, SK_, qlens, klens, 0);

    // masked softmax + split bf16 weights
    dim3 gs(SQ_, B_);
    softmax_split_kernel<<<gs, 256>>>(W, (__nv_bfloat16*)pWs, qlens, klens);

    // context = W V (via Vt, NT form)
    dim3 g2(DV_ / 128, SQ_ / 128, B_);
    gemm_hmma<<<g2, 128, GEMM_SMEM>>>(
        (const __nv_bfloat16*)pWs, (const __nv_bfloat16*)pVt, ctx, K2S, DV_,
        SQ_, DV_, qlens, klens, 1);
}

// round 7
// speedup vs baseline: 11.4132x; 1.3271x over previous
#include <cuda_runtime.h>
#include <cuda_fp16.h>
#include <math.h>
#include <stdint.h>

// Problem constants
#define B_  8
#define SQ_ 2048
#define SK_ 2048
#define D_  1024
#define DV_ 1024

// 2-term fp16 split: each fp32 value becomes 2 fp16 slots.
// A-side [h, h] x B-side [h, l] => ah*bh + ah*bl = ah*(b exact)
// dropped residual: (a - ah)*b ~ 2^-12 relative.
#define K1S (2 * D_)    // 2048
#define K2S (2 * SK_)   // 4096

// ---------------------------------------------------------------------------
// Static scratch
// ---------------------------------------------------------------------------
__device__ __align__(256) __half g_Qs[(size_t)B_ * SQ_ * K1S];
__device__ __align__(256) __half g_Ks[(size_t)B_ * SK_ * K1S];
__device__ __align__(256) __half g_Vt[(size_t)B_ * DV_ * K2S];
__device__ __align__(256) __half g_Ws[(size_t)B_ * SQ_ * K2S];

// ---------------------------------------------------------------------------
// helpers
// ---------------------------------------------------------------------------
__device__ __forceinline__ uint32_t smem_u32(const void* p) {
    uint32_t a;
    asm("{ .reg .u64 t; cvta.to.shared.u64 t, %1; cvt.u32.u64 %0, t; }"
        : "=r"(a) : "l"(p));
    return a;
}

#define SW128(o) ((o) ^ (((o) >> 3) & 0x70))

__device__ __forceinline__ void cp_async16(uint32_t dst, const void* src) {
    asm volatile("cp.async.cg.shared.global [%0], [%1], 16;"
                 :: "r"(dst), "l"(src) : "memory");
}
__device__ __forceinline__ void cp_commit() {
    asm volatile("cp.async.commit_group;" ::: "memory");
}
template <int N>
__device__ __forceinline__ void cp_wait() {
    asm volatile("cp.async.wait_group %0;" :: "n"(N) : "memory");
}

__device__ __forceinline__ void ldm_x4(uint32_t* r, uint32_t a) {
    asm volatile("ldmatrix.sync.aligned.m8n8.x4.shared.b16 {%0,%1,%2,%3}, [%4];"
                 : "=r"(r[0]), "=r"(r[1]), "=r"(r[2]), "=r"(r[3]) : "r"(a));
}

__device__ __forceinline__ void mma16816(float* d, const uint32_t* a, const uint32_t* b) {
    asm volatile(
        "mma.sync.aligned.m16n8k16.row.col.f32.f16.f16.f32 "
        "{%0,%1,%2,%3}, {%4,%5,%6,%7}, {%8,%9}, {%0,%1,%2,%3};"
        : "+f"(d[0]), "+f"(d[1]), "+f"(d[2]), "+f"(d[3])
        : "r"(a[0]), "r"(a[1]), "r"(a[2]), "r"(a[3]), "r"(b[0]), "r"(b[1]));
}

__device__ __forceinline__ void split_hl16(float x, unsigned short& hb, unsigned short& lb) {
    __half h = __float2half_rn(x);
    __half l = __float2half_rn(x - __half2float(h));
    hb = __half_as_ushort(h);
    lb = __half_as_ushort(l);
}

// Pack 8 fp32 values into 16 fp16 slots (2x uint4).
// pat 0 (A-side): per value [h, h]
// pat 1 (B-side): per value [h, l]
__device__ __forceinline__ void pack8h(const float* v, uint4* out, int pat) {
    uint32_t u[8];
#pragma unroll
    for (int i = 0; i < 8; i++) {
        unsigned short hb, lb;
        split_hl16(v[i], hb, lb);
        unsigned short s1 = (pat == 0) ? hb : lb;
        u[i] = (uint32_t)hb | ((uint32_t)s1 << 16);
    }
    out[0] = make_uint4(u[0], u[1], u[2], u[3]);
    out[1] = make_uint4(u[4], u[5], u[6], u[7]);
}

// ---------------------------------------------------------------------------
// fp32 -> 2-slot fp16 split, 8 values/thread, fully vectorized
// ---------------------------------------------------------------------------
__global__ __launch_bounds__(256) void conv_split8_kernel(
    const float* __restrict__ src, __half* __restrict__ dst,
    int n8, float scale, int pat)
{
    int i = blockIdx.x * 256 + threadIdx.x;
    if (i >= n8) return;
    float4 a = ((const float4*)src)[2*i];
    float4 b = ((const float4*)src)[2*i+1];
    float v[8] = {a.x*scale, a.y*scale, a.z*scale, a.w*scale,
                  b.x*scale, b.y*scale, b.z*scale, b.w*scale};
    uint4 o[2];
    pack8h(v, o, pat);
    uint4* d = (uint4*)(dst + (size_t)i * 16);
    d[0] = o[0]; d[1] = o[1];
}

// ---------------------------------------------------------------------------
// V transpose + split: V[b,k,n] -> Vt[b,n,2k+{h,l}], vectorized stores
// ---------------------------------------------------------------------------
__global__ __launch_bounds__(256) void conv_vt_kernel(
    const float* __restrict__ V, __half* __restrict__ Vt)
{
    __shared__ float tile[64][33];
    int b  = blockIdx.z;
    int k0 = blockIdx.y * 64;
    int n0 = blockIdx.x * 32;
    int tid = threadIdx.x;

    const float* Vb = V + (size_t)b * SK_ * DV_;
    int c = tid & 31;
    int r0 = tid >> 5;
#pragma unroll
    for (int p = 0; p < 8; p++) {
        int r = r0 + p * 8;
        tile[r][c] = Vb[(size_t)(k0 + r) * DV_ + n0 + c];
    }
    __syncthreads();

    int n  = tid >> 3;     // 0..31
    int kg = tid & 7;      // 0..7
    float v[8];
#pragma unroll
    for (int i = 0; i < 8; i++) v[i] = tile[kg * 8 + i][n];
    uint4 o[2];
    pack8h(v, o, 1);
    __half* row = Vt + (size_t)b * DV_ * K2S
                + (size_t)(n0 + n) * K2S + 2 * (k0 + kg * 8);
    uint4* d = (uint4*)row;
    d[0] = o[0]; d[1] = o[1];
}

// ---------------------------------------------------------------------------
// Masked softmax (fp32 W in-place) + split fp16 Ws ([h,h]); vectorized,
// Ws writes limited to what GEMM2 actually reads (cols & rows).
// ---------------------------------------------------------------------------
__global__ __launch_bounds__(256) void softmax_split_kernel(
    float* __restrict__ W, __half* __restrict__ Ws,
    const int* __restrict__ qlens, const int* __restrict__ klens)
{
    int q = blockIdx.x;
    int b = blockIdx.y;
    float* row = W + ((size_t)b * SQ_ + q) * SK_;

    int qlen = qlens[b];
    int klen = klens[b];
    int valid = (q < qlen) ? min(klen, q + 1) : 0;

    int tid = threadIdx.x;
    int j0 = tid * 8;
    float4 x0 = ((const float4*)row)[2*tid];
    float4 x1 = ((const float4*)row)[2*tid+1];
    float v[8] = {x0.x, x0.y, x0.z, x0.w, x1.x, x1.y, x1.z, x1.w};

    float mx = -INFINITY;
#pragma unroll
    for (int i = 0; i < 8; i++)
        if (j0 + i < valid) mx = fmaxf(mx, v[i]);

    __shared__ float red[256];
    red[tid] = mx;
    __syncthreads();
#pragma unroll
    for (int s = 128; s > 0; s >>= 1) {
        if (tid < s) red[tid] = fmaxf(red[tid], red[tid + s]);
        __syncthreads();
    }
    mx = red[0];
    __syncthreads();

    float sum = 0.f;
#pragma unroll
    for (int i = 0; i < 8; i++) {
        float e = (j0 + i < valid) ? expf(v[i] - mx) : 0.f;
        v[i] = e;
        sum += e;
    }
    red[tid] = sum;
    __syncthreads();
#pragma unroll
    for (int s = 128; s > 0; s >>= 1) {
        if (tid < s) red[tid] += red[tid + s];
        __syncthreads();
    }
    float denom = red[0];
    float inv = (denom > 0.f) ? (1.f / denom) : 0.f;

#pragma unroll
    for (int i = 0; i < 8; i++) v[i] *= inv;

    ((float4*)row)[2*tid]   = make_float4(v[0], v[1], v[2], v[3]);
    ((float4*)row)[2*tid+1] = make_float4(v[4], v[5], v[6], v[7]);

    // GEMM2 never reads rows q >= ceil128(qlen)
    if (q >= ((qlen + 127) & ~127)) return;
    // GEMM2 reads Ws slots < 2*kmax_tile + 64 => value idx < kmax_tile + 32
    int kmaxt = min(klen, ((q >> 7) + 1) << 7);
    if (j0 < min(SK_, kmaxt + 32)) {
        uint4 o[2];
        pack8h(v, o, 0);
        __half* wsrow = Ws + ((size_t)b * SQ_ + q) * K2S + 2 * j0;
        uint4* d = (uint4*)wsrow;
        d[0] = o[0]; d[1] = o[1];
    }
}

// ---------------------------------------------------------------------------
// HMMA NT GEMM: C[m,n] = sum_k A[m,k]*B[n,k]   (fp16 inputs, fp32 accum)
// CTA 128x128, 4 warps, warp tile 64x64, K-chunk 64, 3-stage cp.async.
// mode 0: scores  — triangular 1D grid (n_tile <= m_tile), skip masked tiles
// mode 1: context — bound K-loop at 2*min(klen, m0+128); zero-fill if m0>=qlen
// ---------------------------------------------------------------------------
#define STAGES 3
#define STAGE_BYTES 32768
#define GEMM_SMEM (STAGES * STAGE_BYTES)

__global__ __launch_bounds__(128, 2) void gemm_hmma(
    const __half* __restrict__ A,
    const __half* __restrict__ Bm,
    float* __restrict__ C, int Kb, int ldc, int M, int N,
    const int* __restrict__ qlens, const int* __restrict__ klens, int mode)
{
    extern __shared__ __align__(1024) char smem[];

    int b = blockIdx.z;
    int m0, n0;
    if (mode == 0) {
        int i = blockIdx.x;
        int mt = (int)((sqrtf(8.0f * i + 1.0f) - 1.0f) * 0.5f);
        while ((mt + 1) * (mt + 2) / 2 <= i) mt++;
        while (mt * (mt + 1) / 2 > i) mt--;
        int nt = i - mt * (mt + 1) / 2;
        m0 = mt * 128; n0 = nt * 128;
    } else {
        m0 = blockIdx.y * 128;
        n0 = blockIdx.x * 128;
    }
    int qlen = qlens[b];
    int klen = klens[b];

    int tid = threadIdx.x;
    int lane = tid & 31;
    int wid = tid >> 5;          // 0..3

    A  += (size_t)b * M * Kb + (size_t)m0 * Kb;
    Bm += (size_t)b * N * Kb + (size_t)n0 * Kb;
    C  += (size_t)b * M * ldc + (size_t)m0 * ldc + n0;

    int nch = Kb >> 6;
    int kmax = min(klen, m0 + 128);
    if (mode == 0) {
        if (m0 >= qlen || n0 >= kmax) return;
    } else {
        if (m0 >= qlen) {
            for (int i = tid; i < 4096; i += 128) {
                int r = i >> 5, c4 = i & 31;
                *(float4*)(C + (size_t)r * ldc + c4 * 4) = make_float4(0.f, 0.f, 0.f, 0.f);
            }
            return;
        }
        int need = (2 * kmax + 63) >> 6;
        nch = min(nch, need);
    }

    uint32_t sb = smem_u32(smem);

    // 2x2 warp grid, 64x64 per warp
    int warp_m = (wid >> 1) * 64;
    int warp_n = (wid & 1) * 64;
    int a_row = warp_m + (lane & 15);
    int a_cb  = (lane >> 4) * 16;
    int b_row = warp_n + (lane & 7) + ((lane >> 4) & 1) * 8;
    int b_cb  = ((lane >> 3) & 1) * 16;

    float acc[4][8][4];
#pragma unroll
    for (int mi = 0; mi < 4; mi++)
#pragma unroll
        for (int ni = 0; ni < 8; ni++)
#pragma unroll
            for (int r = 0; r < 4; r++) acc[mi][ni][r] = 0.f;

    auto load_tile = [&](int s, int c) {
        uint32_t abase = sb + s * STAGE_BYTES;
        uint32_t bbase = abase + 16384;
        const __half* Ac = A + c * 64;
        const __half* Bc = Bm + c * 64;
#pragma unroll
        for (int i = 0; i < 8; i++) {
            int u = tid + i * 128;
            int row = u >> 3, c8 = u & 7;
            uint32_t off = SW128((uint32_t)(row * 128 + c8 * 16));
            cp_async16(abase + off, Ac + (size_t)row * Kb + c8 * 8);
            cp_async16(bbase + off, Bc + (size_t)row * Kb + c8 * 8);
        }
    };

    load_tile(0, 0);
    cp_commit();
    if (nch > 1) { load_tile(1, 1); cp_commit(); }

    for (int c = 0; c < nch; c++) {
        if (c + 1 < nch) cp_wait<1>(); else cp_wait<0>();
        __syncthreads();

        if (c + 2 < nch) { load_tile((c + 2) % STAGES, c + 2); cp_commit(); }

        int s = c % STAGES;
        uint32_t abase = sb + s * STAGE_BYTES;
        uint32_t bbase = abase + 16384;

#pragma unroll
        for (int ks = 0; ks < 4; ks++) {
            uint32_t af[4][4], bf[4][4];
#pragma unroll
            for (int mi = 0; mi < 4; mi++) {
                uint32_t o = (uint32_t)((a_row + mi * 16) * 128 + ks * 32 + a_cb);
                ldm_x4(af[mi], abase + SW128(o));
            }
#pragma unroll
            for (int nj = 0; nj < 4; nj++) {
                uint32_t o = (uint32_t)((b_row + nj * 16) * 128 + ks * 32 + b_cb);
                ldm_x4(bf[nj], bbase + SW128(o));
            }
#pragma unroll
            for (int mi = 0; mi < 4; mi++)
#pragma unroll
                for (int ni = 0; ni < 8; ni++)
                    mma16816(acc[mi][ni], af[mi], &bf[ni >> 1][(ni & 1) * 2]);
        }
    }

    // epilogue
#pragma unroll
    for (int mi = 0; mi < 4; mi++) {
        int r0 = warp_m + mi * 16 + (lane >> 2);
#pragma unroll
        for (int ni = 0; ni < 8; ni++) {
            int cc = warp_n + ni * 8 + (lane & 3) * 2;
            *(float2*)(C + (size_t)r0 * ldc + cc) =
                make_float2(acc[mi][ni][0], acc[mi][ni][1]);
            *(float2*)(C + (size_t)(r0 + 8) * ldc + cc) =
                make_float2(acc[mi][ni][2], acc[mi][ni][3]);
        }
    }
}

// ---------------------------------------------------------------------------
extern "C" void kernel_launch(void* const* d_in, const int* in_sizes, int n_in,
                              void* d_out, int out_size)
{
    const float* Q  = (const float*)d_in[0];
    const float* Kk = (const float*)d_in[1];
    const float* V  = (const float*)d_in[2];
    const int* qlens = (const int*)d_in[3];
    const int* klens = (const int*)d_in[4];

    float* ctx = (float*)d_out;                              // (B, SQ, DV)
    float* W   = (float*)d_out + (size_t)B_ * SQ_ * DV_;     // (B, SQ, SK)

    void *pQs, *pKs, *pVt, *pWs;
    cudaGetSymbolAddress(&pQs, g_Qs);
    cudaGetSymbolAddress(&pKs, g_Ks);
    cudaGetSymbolAddress(&pVt, g_Vt);
    cudaGetSymbolAddress(&pWs, g_Ws);
    cudaFuncSetAttribute(gemm_hmma,
                         cudaFuncAttributeMaxDynamicSharedMemorySize, GEMM_SMEM);

    const int n8 = B_ * SQ_ * D_ / 8;
    // Q scaled by 1/sqrt(D); A-side pattern [h,h]
    conv_split8_kernel<<<n8 / 256, 256>>>(Q, (__half*)pQs, n8, 0.03125f, 0);
    // K: B-side pattern [h,l]
    conv_split8_kernel<<<n8 / 256, 256>>>(Kk, (__half*)pKs, n8, 1.0f, 1);
    dim3 gv(DV_ / 32, SK_ / 64, B_);
    conv_vt_kernel<<<gv, 256>>>(V, (__half*)pVt);

    // S = Q K^T (scale folded into Q) -> weights region (fp32), triangular grid
    dim3 g1(16 * 17 / 2, 1, B_);
    gemm_hmma<<<g1, 128, GEMM_SMEM>>>(
        (const __half*)pQs, (const __half*)pKs, W, K1S, SK_,
        SQ_, SK_, qlens, klens, 0);

    // masked softmax + split fp16 weights
    dim3 gs(SQ_, B_);
    softmax_split_kernel<<<gs, 256>>>(W, (__half*)pWs, qlens, klens);

    // context = W V (via Vt, NT form)
    dim3 g2(DV_ / 128, SQ_ / 128, B_);
    gemm_hmma<<<g2, 128, GEMM_SMEM>>>(
        (const __half*)pWs, (const __half*)pVt, ctx, K2S, DV_,
        SQ_, DV_, qlens, klens, 1);
}

// round 8
// speedup vs baseline: 11.6530x; 1.0210x over previous
#include <cuda_runtime.h>
#include <cuda_fp16.h>
#include <math.h>
#include <stdint.h>

// Problem constants
#define B_  8
#define SQ_ 2048
#define SK_ 2048
#define D_  1024
#define DV_ 1024

// Compensated fp16 scheme: A = high part only (real K), B = two planes (h, l).
// C = Ah*(Bh+Bl) = Ah*B_exact; dropped residual (A-Ah)*B ~ 2^-12 relative.

// ---------------------------------------------------------------------------
// Static scratch
// ---------------------------------------------------------------------------
__device__ __align__(256) __half g_Qh [(size_t)B_ * SQ_ * D_];
__device__ __align__(256) __half g_Kh [(size_t)B_ * SK_ * D_];
__device__ __align__(256) __half g_Kl [(size_t)B_ * SK_ * D_];
__device__ __align__(256) __half g_Vth[(size_t)B_ * DV_ * SK_];
__device__ __align__(256) __half g_Vtl[(size_t)B_ * DV_ * SK_];
__device__ __align__(256) __half g_Wh [(size_t)B_ * SQ_ * SK_];

// ---------------------------------------------------------------------------
// helpers
// ---------------------------------------------------------------------------
__device__ __forceinline__ uint32_t smem_u32(const void* p) {
    uint32_t a;
    asm("{ .reg .u64 t; cvta.to.shared.u64 t, %1; cvt.u32.u64 %0, t; }"
        : "=r"(a) : "l"(p));
    return a;
}

#define SW128(o) ((o) ^ (((o) >> 3) & 0x70))

__device__ __forceinline__ void cp_async16(uint32_t dst, const void* src) {
    asm volatile("cp.async.cg.shared.global [%0], [%1], 16;"
                 :: "r"(dst), "l"(src) : "memory");
}
__device__ __forceinline__ void cp_commit() {
    asm volatile("cp.async.commit_group;" ::: "memory");
}
template <int N>
__device__ __forceinline__ void cp_wait() {
    asm volatile("cp.async.wait_group %0;" :: "n"(N) : "memory");
}

__device__ __forceinline__ void ldm_x4(uint32_t* r, uint32_t a) {
    asm volatile("ldmatrix.sync.aligned.m8n8.x4.shared.b16 {%0,%1,%2,%3}, [%4];"
                 : "=r"(r[0]), "=r"(r[1]), "=r"(r[2]), "=r"(r[3]) : "r"(a));
}

__device__ __forceinline__ void mma16816(float* d, const uint32_t* a, const uint32_t* b) {
    asm volatile(
        "mma.sync.aligned.m16n8k16.row.col.f32.f16.f16.f32 "
        "{%0,%1,%2,%3}, {%4,%5,%6,%7}, {%8,%9}, {%0,%1,%2,%3};"
        : "+f"(d[0]), "+f"(d[1]), "+f"(d[2]), "+f"(d[3])
        : "r"(a[0]), "r"(a[1]), "r"(a[2]), "r"(a[3]), "r"(b[0]), "r"(b[1]));
}

// pack 8 floats -> one uint4 of fp16
__device__ __forceinline__ uint4 pack8_h(const float* v) {
    uint32_t u[4];
#pragma unroll
    for (int j = 0; j < 4; j++) {
        unsigned short a = __half_as_ushort(__float2half_rn(v[2*j]));
        unsigned short b = __half_as_ushort(__float2half_rn(v[2*j+1]));
        u[j] = (uint32_t)a | ((uint32_t)b << 16);
    }
    return make_uint4(u[0], u[1], u[2], u[3]);
}

// split 8 floats into h-plane uint4 and l-plane uint4
__device__ __forceinline__ void pack8_hl(const float* v, uint4& oh, uint4& ol) {
    uint32_t uh[4], ul[4];
#pragma unroll
    for (int j = 0; j < 4; j++) {
        __half h0 = __float2half_rn(v[2*j]);
        __half h1 = __float2half_rn(v[2*j+1]);
        __half l0 = __float2half_rn(v[2*j]   - __half2float(h0));
        __half l1 = __float2half_rn(v[2*j+1] - __half2float(h1));
        uh[j] = (uint32_t)__half_as_ushort(h0) | ((uint32_t)__half_as_ushort(h1) << 16);
        ul[j] = (uint32_t)__half_as_ushort(l0) | ((uint32_t)__half_as_ushort(l1) << 16);
    }
    oh = make_uint4(uh[0], uh[1], uh[2], uh[3]);
    ol = make_uint4(ul[0], ul[1], ul[2], ul[3]);
}

// ---------------------------------------------------------------------------
// Q: fp32 -> fp16 high only (scaled)
// ---------------------------------------------------------------------------
__global__ __launch_bounds__(256) void conv_h_kernel(
    const float* __restrict__ src, __half* __restrict__ dst, int n8, float scale)
{
    int i = blockIdx.x * 256 + threadIdx.x;
    if (i >= n8) return;
    float4 a = ((const float4*)src)[2*i];
    float4 b = ((const float4*)src)[2*i+1];
    float v[8] = {a.x*scale, a.y*scale, a.z*scale, a.w*scale,
                  b.x*scale, b.y*scale, b.z*scale, b.w*scale};
    ((uint4*)dst)[i] = pack8_h(v);
}

// ---------------------------------------------------------------------------
// K: fp32 -> h plane + l plane
// ---------------------------------------------------------------------------
__global__ __launch_bounds__(256) void conv_hl_kernel(
    const float* __restrict__ src, __half* __restrict__ dh,
    __half* __restrict__ dl, int n8)
{
    int i = blockIdx.x * 256 + threadIdx.x;
    if (i >= n8) return;
    float4 a = ((const float4*)src)[2*i];
    float4 b = ((const float4*)src)[2*i+1];
    float v[8] = {a.x, a.y, a.z, a.w, b.x, b.y, b.z, b.w};
    uint4 oh, ol;
    pack8_hl(v, oh, ol);
    ((uint4*)dh)[i] = oh;
    ((uint4*)dl)[i] = ol;
}

// ---------------------------------------------------------------------------
// V transpose + split: V[b,k,n] -> Vth/Vtl [b,n,k]
// ---------------------------------------------------------------------------
__global__ __launch_bounds__(256) void conv_vt_kernel(
    const float* __restrict__ V, __half* __restrict__ Vth, __half* __restrict__ Vtl)
{
    __shared__ float tile[64][33];
    int b  = blockIdx.z;
    int k0 = blockIdx.y * 64;
    int n0 = blockIdx.x * 32;
    int tid = threadIdx.x;

    const float* Vb = V + (size_t)b * SK_ * DV_;
    int c = tid & 31;
    int r0 = tid >> 5;
#pragma unroll
    for (int p = 0; p < 8; p++) {
        int r = r0 + p * 8;
        tile[r][c] = Vb[(size_t)(k0 + r) * DV_ + n0 + c];
    }
    __syncthreads();

    int n  = tid >> 3;     // 0..31
    int kg = tid & 7;      // 0..7
    float v[8];
#pragma unroll
    for (int i = 0; i < 8; i++) v[i] = tile[kg * 8 + i][n];
    uint4 oh, ol;
    pack8_hl(v, oh, ol);
    size_t off = (size_t)b * DV_ * SK_ + (size_t)(n0 + n) * SK_ + k0 + kg * 8;
    *(uint4*)(Vth + off) = oh;
    *(uint4*)(Vtl + off) = ol;
}

// ---------------------------------------------------------------------------
// Masked softmax (fp32 W in-place) + fp16 high Wh; writes limited to what
// GEMM2 actually reads.
// ---------------------------------------------------------------------------
__global__ __launch_bounds__(256) void softmax_split_kernel(
    float* __restrict__ W, __half* __restrict__ Wh,
    const int* __restrict__ qlens, const int* __restrict__ klens)
{
    int q = blockIdx.x;
    int b = blockIdx.y;
    float* row = W + ((size_t)b * SQ_ + q) * SK_;

    int qlen = qlens[b];
    int klen = klens[b];
    int valid = (q < qlen) ? min(klen, q + 1) : 0;

    int tid = threadIdx.x;
    int j0 = tid * 8;
    float4 x0 = ((const float4*)row)[2*tid];
    float4 x1 = ((const float4*)row)[2*tid+1];
    float v[8] = {x0.x, x0.y, x0.z, x0.w, x1.x, x1.y, x1.z, x1.w};

    float mx = -INFINITY;
#pragma unroll
    for (int i = 0; i < 8; i++)
        if (j0 + i < valid) mx = fmaxf(mx, v[i]);

    __shared__ float red[256];
    red[tid] = mx;
    __syncthreads();
#pragma unroll
    for (int s = 128; s > 0; s >>= 1) {
        if (tid < s) red[tid] = fmaxf(red[tid], red[tid + s]);
        __syncthreads();
    }
    mx = red[0];
    __syncthreads();

    float sum = 0.f;
#pragma unroll
    for (int i = 0; i < 8; i++) {
        float e = (j0 + i < valid) ? expf(v[i] - mx) : 0.f;
        v[i] = e;
        sum += e;
    }
    red[tid] = sum;
    __syncthreads();
#pragma unroll
    for (int s = 128; s > 0; s >>= 1) {
        if (tid < s) red[tid] += red[tid + s];
        __syncthreads();
    }
    float denom = red[0];
    float inv = (denom > 0.f) ? (1.f / denom) : 0.f;

#pragma unroll
    for (int i = 0; i < 8; i++) v[i] *= inv;

    ((float4*)row)[2*tid]   = make_float4(v[0], v[1], v[2], v[3]);
    ((float4*)row)[2*tid+1] = make_float4(v[4], v[5], v[6], v[7]);

    // GEMM2 never reads rows q >= ceil128(qlen)
    if (q >= ((qlen + 127) & ~127)) return;
    // GEMM2 reads cols < ceil(kmax_tile/64)*64 <= kmax_tile + 63
    int kmaxt = min(klen, ((q >> 7) + 1) << 7);
    if (j0 < min(SK_, kmaxt + 64)) {
        __half* whrow = Wh + ((size_t)b * SQ_ + q) * SK_ + j0;
        *(uint4*)whrow = pack8_h(v);
    }
}

// ---------------------------------------------------------------------------
// Compensated HMMA NT GEMM: C[m,n] = sum_k A[m,k]*(Bh[n,k]+Bl[n,k])
// CTA 128x128, 4 warps, warp tile 64x64. K-chunk 64 (real), 2-stage cp.async.
// Stage: A 16KB + Bh 16KB + Bl 16KB = 48KB; 2 stages = 96KB; 2 CTAs/SM.
// mode 0: scores  — triangular 1D grid (n_tile <= m_tile), skip masked tiles
// mode 1: context — bound K-loop at min(klen, m0+128); zero-fill if m0>=qlen
// ---------------------------------------------------------------------------
#define STAGE_BYTES 49152
#define GEMM_SMEM (2 * STAGE_BYTES)

__global__ __launch_bounds__(128, 2) void gemm_hmma(
    const __half* __restrict__ A,
    const __half* __restrict__ Bh,
    const __half* __restrict__ Bl,
    float* __restrict__ C, int Kb, int ldc, int M, int N,
    const int* __restrict__ qlens, const int* __restrict__ klens, int mode)
{
    extern __shared__ __align__(1024) char smem[];

    int b = blockIdx.z;
    int m0, n0;
    if (mode == 0) {
        int i = blockIdx.x;
        int mt = (int)((sqrtf(8.0f * i + 1.0f) - 1.0f) * 0.5f);
        while ((mt + 1) * (mt + 2) / 2 <= i) mt++;
        while (mt * (mt + 1) / 2 > i) mt--;
        int nt = i - mt * (mt + 1) / 2;
        m0 = mt * 128; n0 = nt * 128;
    } else {
        m0 = blockIdx.y * 128;
        n0 = blockIdx.x * 128;
    }
    int qlen = qlens[b];
    int klen = klens[b];

    int tid = threadIdx.x;
    int lane = tid & 31;
    int wid = tid >> 5;

    A  += (size_t)b * M * Kb + (size_t)m0 * Kb;
    Bh += (size_t)b * N * Kb + (size_t)n0 * Kb;
    Bl += (size_t)b * N * Kb + (size_t)n0 * Kb;
    C  += (size_t)b * M * ldc + (size_t)m0 * ldc + n0;

    int nch = Kb >> 6;
    int kmax = min(klen, m0 + 128);
    if (mode == 0) {
        if (m0 >= qlen || n0 >= kmax) return;
    } else {
        if (m0 >= qlen) {
            for (int i = tid; i < 4096; i += 128) {
                int r = i >> 5, c4 = i & 31;
                *(float4*)(C + (size_t)r * ldc + c4 * 4) = make_float4(0.f, 0.f, 0.f, 0.f);
            }
            return;
        }
        nch = min(nch, (kmax + 63) >> 6);
    }

    uint32_t sb = smem_u32(smem);

    // 2x2 warp grid, 64x64 per warp
    int warp_m = (wid >> 1) * 64;
    int warp_n = (wid & 1) * 64;
    int a_row = warp_m + (lane & 15);
    int a_cb  = (lane >> 4) * 16;
    int b_row = warp_n + (lane & 7) + ((lane >> 4) & 1) * 8;
    int b_cb  = ((lane >> 3) & 1) * 16;

    float acc[4][8][4];
#pragma unroll
    for (int mi = 0; mi < 4; mi++)
#pragma unroll
        for (int ni = 0; ni < 8; ni++)
#pragma unroll
            for (int r = 0; r < 4; r++) acc[mi][ni][r] = 0.f;

    // Stage layout: [A 16KB][Bh 16KB][Bl 16KB]
    auto load_tile = [&](int s, int c) {
        uint32_t abase  = sb + s * STAGE_BYTES;
        uint32_t bhbase = abase + 16384;
        uint32_t blbase = abase + 32768;
        const __half* Ac  = A  + c * 64;
        const __half* Bhc = Bh + c * 64;
        const __half* Blc = Bl + c * 64;
#pragma unroll
        for (int i = 0; i < 8; i++) {
            int u = tid + i * 128;
            int row = u >> 3, c8 = u & 7;
            size_t goff = (size_t)row * Kb + c8 * 8;
            uint32_t off = SW128((uint32_t)(row * 128 + c8 * 16));
            cp_async16(abase  + off, Ac  + goff);
            cp_async16(bhbase + off, Bhc + goff);
            cp_async16(blbase + off, Blc + goff);
        }
    };

    load_tile(0, 0);
    cp_commit();

    for (int c = 0; c < nch; c++) {
        cp_wait<0>();
        __syncthreads();

        if (c + 1 < nch) { load_tile((c + 1) & 1, c + 1); cp_commit(); }

        int s = c & 1;
        uint32_t abase  = sb + s * STAGE_BYTES;
        uint32_t bhbase = abase + 16384;
        uint32_t blbase = abase + 32768;

#pragma unroll
        for (int ks = 0; ks < 4; ks++) {
            uint32_t af[4][4], bfh[4][4], bfl[4][4];
#pragma unroll
            for (int mi = 0; mi < 4; mi++) {
                uint32_t o = (uint32_t)((a_row + mi * 16) * 128 + ks * 32 + a_cb);
                ldm_x4(af[mi], abase + SW128(o));
            }
#pragma unroll
            for (int nj = 0; nj < 4; nj++) {
                uint32_t o = (uint32_t)((b_row + nj * 16) * 128 + ks * 32 + b_cb);
                ldm_x4(bfh[nj], bhbase + SW128(o));
                ldm_x4(bfl[nj], blbase + SW128(o));
            }
#pragma unroll
            for (int mi = 0; mi < 4; mi++)
#pragma unroll
                for (int ni = 0; ni < 8; ni++) {
                    mma16816(acc[mi][ni], af[mi], &bfh[ni >> 1][(ni & 1) * 2]);
                    mma16816(acc[mi][ni], af[mi], &bfl[ni >> 1][(ni & 1) * 2]);
                }
        }
    }

    // epilogue
#pragma unroll
    for (int mi = 0; mi < 4; mi++) {
        int r0 = warp_m + mi * 16 + (lane >> 2);
#pragma unroll
        for (int ni = 0; ni < 8; ni++) {
            int cc = warp_n + ni * 8 + (lane & 3) * 2;
            *(float2*)(C + (size_t)r0 * ldc + cc) =
                make_float2(acc[mi][ni][0], acc[mi][ni][1]);
            *(float2*)(C + (size_t)(r0 + 8) * ldc + cc) =
                make_float2(acc[mi][ni][2], acc[mi][ni][3]);
        }
    }
}

// ---------------------------------------------------------------------------
extern "C" void kernel_launch(void* const* d_in, const int* in_sizes, int n_in,
                              void* d_out, int out_size)
{
    const float* Q  = (const float*)d_in[0];
    const float* Kk = (const float*)d_in[1];
    const float* V  = (const float*)d_in[2];
    const int* qlens = (const int*)d_in[3];
    const int* klens = (const int*)d_in[4];

    float* ctx = (float*)d_out;                              // (B, SQ, DV)
    float* W   = (float*)d_out + (size_t)B_ * SQ_ * DV_;     // (B, SQ, SK)

    void *pQh, *pKh, *pKl, *pVth, *pVtl, *pWh;
    cudaGetSymbolAddress(&pQh, g_Qh);
    cudaGetSymbolAddress(&pKh, g_Kh);
    cudaGetSymbolAddress(&pKl, g_Kl);
    cudaGetSymbolAddress(&pVth, g_Vth);
    cudaGetSymbolAddress(&pVtl, g_Vtl);
    cudaGetSymbolAddress(&pWh, g_Wh);
    cudaFuncSetAttribute(gemm_hmma,
                         cudaFuncAttributeMaxDynamicSharedMemorySize, GEMM_SMEM);

    const int n8 = B_ * SQ_ * D_ / 8;
    // Q scaled by 1/sqrt(D), high part only
    conv_h_kernel<<<n8 / 256, 256>>>(Q, (__half*)pQh, n8, 0.03125f);
    // K: h + l planes
    conv_hl_kernel<<<n8 / 256, 256>>>(Kk, (__half*)pKh, (__half*)pKl, n8);
    // V transpose + h/l planes
    dim3 gv(DV_ / 32, SK_ / 64, B_);
    conv_vt_kernel<<<gv, 256>>>(V, (__half*)pVth, (__half*)pVtl);

    // S = Qh (Kh+Kl)^T -> weights region (fp32), triangular grid
    dim3 g1(16 * 17 / 2, 1, B_);
    gemm_hmma<<<g1, 128, GEMM_SMEM>>>(
        (const __half*)pQh, (const __half*)pKh, (const __half*)pKl, W,
        D_, SK_, SQ_, SK_, qlens, klens, 0);

    // masked softmax + fp16 high weights
    dim3 gs(SQ_, B_);
    softmax_split_kernel<<<gs, 256>>>(W, (__half*)pWh, qlens, klens);

    // context = Wh (Vth+Vtl)^T
    dim3 g2(DV_ / 128, SQ_ / 128, B_);
    gemm_hmma<<<g2, 128, GEMM_SMEM>>>(
        (const __half*)pWh, (const __half*)pVth, (const __half*)pVtl, ctx,
        SK_, DV_, SQ_, DV_, qlens, klens, 1);
}

// round 9
// speedup vs baseline: 15.6106x; 1.3396x over previous
#include <cuda_runtime.h>
#include <cuda_fp16.h>
#include <math.h>
#include <stdint.h>

// Problem constants
#define B_  8
#define SQ_ 2048
#define SK_ 2048
#define D_  1024
#define DV_ 1024

// Compensated fp16 scheme:
//  GEMM1: S = Qh x (Kh + Kl)^T  (2 B-planes; K exact to ~2^-22)
//  GEMM2: ctx = Wh x Vh^T       (1 plane; W,V residuals each ~2^-12 RMS)

// ---------------------------------------------------------------------------
// Static scratch
// ---------------------------------------------------------------------------
__device__ __align__(256) __half g_Qh [(size_t)B_ * SQ_ * D_];
__device__ __align__(256) __half g_Kh [(size_t)B_ * SK_ * D_];
__device__ __align__(256) __half g_Kl [(size_t)B_ * SK_ * D_];
__device__ __align__(256) __half g_Vth[(size_t)B_ * DV_ * SK_];
__device__ __align__(256) __half g_Wh [(size_t)B_ * SQ_ * SK_];

// ---------------------------------------------------------------------------
// helpers
// ---------------------------------------------------------------------------
__device__ __forceinline__ uint32_t smem_u32(const void* p) {
    uint32_t a;
    asm("{ .reg .u64 t; cvta.to.shared.u64 t, %1; cvt.u32.u64 %0, t; }"
        : "=r"(a) : "l"(p));
    return a;
}

#define SW128(o) ((o) ^ (((o) >> 3) & 0x70))

__device__ __forceinline__ void cp_async16(uint32_t dst, const void* src) {
    asm volatile("cp.async.cg.shared.global [%0], [%1], 16;"
                 :: "r"(dst), "l"(src) : "memory");
}
__device__ __forceinline__ void cp_commit() {
    asm volatile("cp.async.commit_group;" ::: "memory");
}
template <int N>
__device__ __forceinline__ void cp_wait() {
    asm volatile("cp.async.wait_group %0;" :: "n"(N) : "memory");
}

__device__ __forceinline__ void ldm_x4(uint32_t* r, uint32_t a) {
    asm volatile("ldmatrix.sync.aligned.m8n8.x4.shared.b16 {%0,%1,%2,%3}, [%4];"
                 : "=r"(r[0]), "=r"(r[1]), "=r"(r[2]), "=r"(r[3]) : "r"(a));
}

__device__ __forceinline__ void mma16816(float* d, const uint32_t* a, const uint32_t* b) {
    asm volatile(
        "mma.sync.aligned.m16n8k16.row.col.f32.f16.f16.f32 "
        "{%0,%1,%2,%3}, {%4,%5,%6,%7}, {%8,%9}, {%0,%1,%2,%3};"
        : "+f"(d[0]), "+f"(d[1]), "+f"(d[2]), "+f"(d[3])
        : "r"(a[0]), "r"(a[1]), "r"(a[2]), "r"(a[3]), "r"(b[0]), "r"(b[1]));
}

// pack 8 floats -> one uint4 of fp16 (high parts)
__device__ __forceinline__ uint4 pack8_h(const float* v) {
    uint32_t u[4];
#pragma unroll
    for (int j = 0; j < 4; j++) {
        unsigned short a = __half_as_ushort(__float2half_rn(v[2*j]));
        unsigned short b = __half_as_ushort(__float2half_rn(v[2*j+1]));
        u[j] = (uint32_t)a | ((uint32_t)b << 16);
    }
    return make_uint4(u[0], u[1], u[2], u[3]);
}

// split 8 floats into h-plane + l-plane uint4s
__device__ __forceinline__ void pack8_hl(const float* v, uint4& oh, uint4& ol) {
    uint32_t uh[4], ul[4];
#pragma unroll
    for (int j = 0; j < 4; j++) {
        __half h0 = __float2half_rn(v[2*j]);
        __half h1 = __float2half_rn(v[2*j+1]);
        __half l0 = __float2half_rn(v[2*j]   - __half2float(h0));
        __half l1 = __float2half_rn(v[2*j+1] - __half2float(h1));
        uh[j] = (uint32_t)__half_as_ushort(h0) | ((uint32_t)__half_as_ushort(h1) << 16);
        ul[j] = (uint32_t)__half_as_ushort(l0) | ((uint32_t)__half_as_ushort(l1) << 16);
    }
    oh = make_uint4(uh[0], uh[1], uh[2], uh[3]);
    ol = make_uint4(ul[0], ul[1], ul[2], ul[3]);
}

// ---------------------------------------------------------------------------
// Q: fp32 -> fp16 high (scaled); skip rows >= ceil128(qlen).
// Block: 256 thr, 2 rows (1024 cols each). grid (SQ/2, B)
// ---------------------------------------------------------------------------
__global__ __launch_bounds__(256) void conv_q_kernel(
    const float* __restrict__ Q, __half* __restrict__ dst,
    const int* __restrict__ qlens, float scale)
{
    int b = blockIdx.y;
    int q0 = blockIdx.x * 2;
    if (q0 >= ((qlens[b] + 127) & ~127)) return;
    int tid = threadIdx.x;
    int row = q0 + (tid >> 7);
    int c8  = tid & 127;
    size_t i = ((size_t)b * SQ_ + row) * (D_ / 8) + c8;
    float4 a = ((const float4*)Q)[2*i];
    float4 c = ((const float4*)Q)[2*i+1];
    float v[8] = {a.x*scale, a.y*scale, a.z*scale, a.w*scale,
                  c.x*scale, c.y*scale, c.z*scale, c.w*scale};
    ((uint4*)dst)[i] = pack8_h(v);
}

// ---------------------------------------------------------------------------
// K: fp32 -> h + l planes; skip rows >= ceil128(klen).
// ---------------------------------------------------------------------------
__global__ __launch_bounds__(256) void conv_k_kernel(
    const float* __restrict__ Kk, __half* __restrict__ dh,
    __half* __restrict__ dl, const int* __restrict__ klens)
{
    int b = blockIdx.y;
    int r0 = blockIdx.x * 2;
    if (r0 >= ((klens[b] + 127) & ~127)) return;
    int tid = threadIdx.x;
    int row = r0 + (tid >> 7);
    int c8  = tid & 127;
    size_t i = ((size_t)b * SK_ + row) * (D_ / 8) + c8;
    float4 a = ((const float4*)Kk)[2*i];
    float4 c = ((const float4*)Kk)[2*i+1];
    float v[8] = {a.x, a.y, a.z, a.w, c.x, c.y, c.z, c.w};
    uint4 oh, ol;
    pack8_hl(v, oh, ol);
    ((uint4*)dh)[i] = oh;
    ((uint4*)dl)[i] = ol;
}

// ---------------------------------------------------------------------------
// V transpose (high only): V[b,k,n] -> Vth[b,n,k]; skip k0 >= ceil64(klen)
// ---------------------------------------------------------------------------
__global__ __launch_bounds__(256) void conv_vt_kernel(
    const float* __restrict__ V, __half* __restrict__ Vth,
    const int* __restrict__ klens)
{
    int b  = blockIdx.z;
    int k0 = blockIdx.y * 64;
    if (k0 >= ((klens[b] + 63) & ~63)) return;
    __shared__ float tile[64][33];
    int n0 = blockIdx.x * 32;
    int tid = threadIdx.x;

    const float* Vb = V + (size_t)b * SK_ * DV_;
    int c = tid & 31;
    int r0 = tid >> 5;
#pragma unroll
    for (int p = 0; p < 8; p++) {
        int r = r0 + p * 8;
        tile[r][c] = Vb[(size_t)(k0 + r) * DV_ + n0 + c];
    }
    __syncthreads();

    int n  = tid >> 3;     // 0..31
    int kg = tid & 7;      // 0..7
    float v[8];
#pragma unroll
    for (int i = 0; i < 8; i++) v[i] = tile[kg * 8 + i][n];
    size_t off = (size_t)b * DV_ * SK_ + (size_t)(n0 + n) * SK_ + k0 + kg * 8;
    *(uint4*)(Vth + off) = pack8_h(v);
}

// ---------------------------------------------------------------------------
// Masked softmax (fp32 W in-place) + fp16 Wh; reads only valid cols,
// Wh writes limited to what GEMM2 reads.
// ---------------------------------------------------------------------------
__global__ __launch_bounds__(256) void softmax_split_kernel(
    float* __restrict__ W, __half* __restrict__ Wh,
    const int* __restrict__ qlens, const int* __restrict__ klens)
{
    int q = blockIdx.x;
    int b = blockIdx.y;
    float* row = W + ((size_t)b * SQ_ + q) * SK_;

    int qlen = qlens[b];
    int klen = klens[b];
    int valid = (q < qlen) ? min(klen, q + 1) : 0;

    int tid = threadIdx.x;
    int j0 = tid * 8;
    float v[8] = {0.f, 0.f, 0.f, 0.f, 0.f, 0.f, 0.f, 0.f};
    if (j0 < valid) {
        float4 x0 = ((const float4*)row)[2*tid];
        float4 x1 = ((const float4*)row)[2*tid+1];
        v[0]=x0.x; v[1]=x0.y; v[2]=x0.z; v[3]=x0.w;
        v[4]=x1.x; v[5]=x1.y; v[6]=x1.z; v[7]=x1.w;
    }

    float mx = -INFINITY;
#pragma unroll
    for (int i = 0; i < 8; i++)
        if (j0 + i < valid) mx = fmaxf(mx, v[i]);

    __shared__ float red[256];
    red[tid] = mx;
    __syncthreads();
#pragma unroll
    for (int s = 128; s > 0; s >>= 1) {
        if (tid < s) red[tid] = fmaxf(red[tid], red[tid + s]);
        __syncthreads();
    }
    mx = red[0];
    __syncthreads();

    float sum = 0.f;
#pragma unroll
    for (int i = 0; i < 8; i++) {
        float e = (j0 + i < valid) ? expf(v[i] - mx) : 0.f;
        v[i] = e;
        sum += e;
    }
    red[tid] = sum;
    __syncthreads();
#pragma unroll
    for (int s = 128; s > 0; s >>= 1) {
        if (tid < s) red[tid] += red[tid + s];
        __syncthreads();
    }
    float denom = red[0];
    float inv = (denom > 0.f) ? (1.f / denom) : 0.f;

#pragma unroll
    for (int i = 0; i < 8; i++) v[i] *= inv;

    ((float4*)row)[2*tid]   = make_float4(v[0], v[1], v[2], v[3]);
    ((float4*)row)[2*tid+1] = make_float4(v[4], v[5], v[6], v[7]);

    // GEMM2 never reads rows q >= ceil128(qlen)
    if (q >= ((qlen + 127) & ~127)) return;
    // GEMM2 reads cols < ceil64(min(klen, m0+128))
    int kmaxt = min(klen, ((q >> 7) + 1) << 7);
    if (j0 < min(SK_, kmaxt + 64)) {
        __half* whrow = Wh + ((size_t)b * SQ_ + q) * SK_ + j0;
        *(uint4*)whrow = pack8_h(v);
    }
}

// ---------------------------------------------------------------------------
// Compensated HMMA NT GEMM: C = A x (Bh [+ Bl])^T, fp32 accum.
// CTA 128x128, 4 warps (64x64 each), K-chunk 64, 2-stage cp.async.
// PLANES=2: B-fragment buffer reused across planes (reg pressure).
// mode 0: scores  — triangular 1D grid, skip masked tiles
// mode 1: context — K-loop bound ceil64(min(klen, m0+128)); zero if m0>=qlen
// ---------------------------------------------------------------------------
template <int PLANES>
__global__ __launch_bounds__(128, 2) void gemm_hmma(
    const __half* __restrict__ A,
    const __half* __restrict__ Bh,
    const __half* __restrict__ Bl,
    float* __restrict__ C, int Kb, int ldc, int M, int N,
    const int* __restrict__ qlens, const int* __restrict__ klens, int mode)
{
    constexpr int STAGE_BYTES = 16384 * (1 + PLANES);
    extern __shared__ __align__(1024) char smem[];

    int b = blockIdx.z;
    int m0, n0;
    if (mode == 0) {
        int i = blockIdx.x;
        int mt = (int)((sqrtf(8.0f * i + 1.0f) - 1.0f) * 0.5f);
        while ((mt + 1) * (mt + 2) / 2 <= i) mt++;
        while (mt * (mt + 1) / 2 > i) mt--;
        int nt = i - mt * (mt + 1) / 2;
        m0 = mt * 128; n0 = nt * 128;
    } else {
        m0 = blockIdx.y * 128;
        n0 = blockIdx.x * 128;
    }
    int qlen = qlens[b];
    int klen = klens[b];

    int tid = threadIdx.x;
    int lane = tid & 31;
    int wid = tid >> 5;

    A  += (size_t)b * M * Kb + (size_t)m0 * Kb;
    Bh += (size_t)b * N * Kb + (size_t)n0 * Kb;
    if (PLANES == 2) Bl += (size_t)b * N * Kb + (size_t)n0 * Kb;
    C  += (size_t)b * M * ldc + (size_t)m0 * ldc + n0;

    int nch = Kb >> 6;
    int kmax = min(klen, m0 + 128);
    if (mode == 0) {
        if (m0 >= qlen || n0 >= kmax) return;
    } else {
        if (m0 >= qlen) {
            for (int i = tid; i < 4096; i += 128) {
                int r = i >> 5, c4 = i & 31;
                *(float4*)(C + (size_t)r * ldc + c4 * 4) = make_float4(0.f, 0.f, 0.f, 0.f);
            }
            return;
        }
        nch = min(nch, (kmax + 63) >> 6);
    }

    uint32_t sb = smem_u32(smem);

    int warp_m = (wid >> 1) * 64;
    int warp_n = (wid & 1) * 64;
    int a_row = warp_m + (lane & 15);
    int a_cb  = (lane >> 4) * 16;
    int b_row = warp_n + (lane & 7) + ((lane >> 4) & 1) * 8;
    int b_cb  = ((lane >> 3) & 1) * 16;

    float acc[4][8][4];
#pragma unroll
    for (int mi = 0; mi < 4; mi++)
#pragma unroll
        for (int ni = 0; ni < 8; ni++)
#pragma unroll
            for (int r = 0; r < 4; r++) acc[mi][ni][r] = 0.f;

    auto load_tile = [&](int s, int c) {
        uint32_t abase  = sb + s * STAGE_BYTES;
        const __half* Ac  = A  + c * 64;
        const __half* Bhc = Bh + c * 64;
        const __half* Blc = (PLANES == 2) ? (Bl + c * 64) : nullptr;
#pragma unroll
        for (int i = 0; i < 8; i++) {
            int u = tid + i * 128;
            int row = u >> 3, c8 = u & 7;
            size_t goff = (size_t)row * Kb + c8 * 8;
            uint32_t off = SW128((uint32_t)(row * 128 + c8 * 16));
            cp_async16(abase + off, Ac + goff);
            cp_async16(abase + 16384 + off, Bhc + goff);
            if (PLANES == 2) cp_async16(abase + 32768 + off, Blc + goff);
        }
    };

    load_tile(0, 0);
    cp_commit();

    for (int c = 0; c < nch; c++) {
        cp_wait<0>();
        __syncthreads();

        if (c + 1 < nch) { load_tile((c + 1) & 1, c + 1); cp_commit(); }

        uint32_t abase = sb + (c & 1) * STAGE_BYTES;

#pragma unroll
        for (int ks = 0; ks < 4; ks++) {
            uint32_t af[4][4], bf[4][4];
#pragma unroll
            for (int mi = 0; mi < 4; mi++) {
                uint32_t o = (uint32_t)((a_row + mi * 16) * 128 + ks * 32 + a_cb);
                ldm_x4(af[mi], abase + SW128(o));
            }
#pragma unroll
            for (int p = 0; p < PLANES; p++) {
                uint32_t pbase = abase + 16384 * (1 + p);
#pragma unroll
                for (int nj = 0; nj < 4; nj++) {
                    uint32_t o = (uint32_t)((b_row + nj * 16) * 128 + ks * 32 + b_cb);
                    ldm_x4(bf[nj], pbase + SW128(o));
                }
#pragma unroll
                for (int mi = 0; mi < 4; mi++)
#pragma unroll
                    for (int ni = 0; ni < 8; ni++)
                        mma16816(acc[mi][ni], af[mi], &bf[ni >> 1][(ni & 1) * 2]);
            }
        }
    }

    // epilogue
#pragma unroll
    for (int mi = 0; mi < 4; mi++) {
        int r0 = warp_m + mi * 16 + (lane >> 2);
#pragma unroll
        for (int ni = 0; ni < 8; ni++) {
            int cc = warp_n + ni * 8 + (lane & 3) * 2;
            *(float2*)(C + (size_t)r0 * ldc + cc) =
                make_float2(acc[mi][ni][0], acc[mi][ni][1]);
            *(float2*)(C + (size_t)(r0 + 8) * ldc + cc) =
                make_float2(acc[mi][ni][2], acc[mi][ni][3]);
        }
    }
}

// ---------------------------------------------------------------------------
extern "C" void kernel_launch(void* const* d_in, const int* in_sizes, int n_in,
                              void* d_out, int out_size)
{
    const float* Q  = (const float*)d_in[0];
    const float* Kk = (const float*)d_in[1];
    const float* V  = (const float*)d_in[2];
    const int* qlens = (const int*)d_in[3];
    const int* klens = (const int*)d_in[4];

    float* ctx = (float*)d_out;                              // (B, SQ, DV)
    float* W   = (float*)d_out + (size_t)B_ * SQ_ * DV_;     // (B, SQ, SK)

    void *pQh, *pKh, *pKl, *pVth, *pWh;
    cudaGetSymbolAddress(&pQh, g_Qh);
    cudaGetSymbolAddress(&pKh, g_Kh);
    cudaGetSymbolAddress(&pKl, g_Kl);
    cudaGetSymbolAddress(&pVth, g_Vth);
    cudaGetSymbolAddress(&pWh, g_Wh);
    cudaFuncSetAttribute(gemm_hmma<2>,
                         cudaFuncAttributeMaxDynamicSharedMemorySize, 2 * 49152);
    cudaFuncSetAttribute(gemm_hmma<1>,
                         cudaFuncAttributeMaxDynamicSharedMemorySize, 2 * 32768);

    // conversions (mask-aware row skipping)
    dim3 gq(SQ_ / 2, B_);
    conv_q_kernel<<<gq, 256>>>(Q, (__half*)pQh, qlens, 0.03125f);
    conv_k_kernel<<<gq, 256>>>(Kk, (__half*)pKh, (__half*)pKl, klens);
    dim3 gv(DV_ / 32, SK_ / 64, B_);
    conv_vt_kernel<<<gv, 256>>>(V, (__half*)pVth, klens);

    // S = Qh (Kh+Kl)^T -> weights region (fp32), triangular grid
    dim3 g1(16 * 17 / 2, 1, B_);
    gemm_hmma<2><<<g1, 128, 2 * 49152>>>(
        (const __half*)pQh, (const __half*)pKh, (const __half*)pKl, W,
        D_, SK_, SQ_, SK_, qlens, klens, 0);

    // masked softmax + fp16 weights
    dim3 gs(SQ_, B_);
    softmax_split_kernel<<<gs, 256>>>(W, (__half*)pWh, qlens, klens);

    // context = Wh Vth^T (single plane)
    dim3 g2(DV_ / 128, SQ_ / 128, B_);
    gemm_hmma<1><<<g2, 128, 2 * 32768>>>(
        (const __half*)pWh, (const __half*)pVth, (const __half*)pVth, ctx,
        SK_, DV_, SQ_, DV_, qlens, klens, 1);
}

// round 10
// speedup vs baseline: 20.4163x; 1.3078x over previous
#include <cuda_runtime.h>
#include <cuda_fp16.h>
#include <math.h>
#include <stdint.h>

// Problem constants
#define B_  8
#define SQ_ 2048
#define SK_ 2048
#define D_  1024
#define DV_ 1024

// Plain fp16 GEMMs with fp32 accumulate; aggregate rounding ~4-6e-4 rel,
// under the 1e-3 budget (measured composition across rounds).

// ---------------------------------------------------------------------------
// Static scratch
// ---------------------------------------------------------------------------
__device__ __align__(256) __half g_Qh [(size_t)B_ * SQ_ * D_];
__device__ __align__(256) __half g_Kh [(size_t)B_ * SK_ * D_];
__device__ __align__(256) __half g_Vth[(size_t)B_ * DV_ * SK_];
__device__ __align__(256) __half g_Wh [(size_t)B_ * SQ_ * SK_];

// ---------------------------------------------------------------------------
// helpers
// ---------------------------------------------------------------------------
__device__ __forceinline__ uint32_t smem_u32(const void* p) {
    uint32_t a;
    asm("{ .reg .u64 t; cvta.to.shared.u64 t, %1; cvt.u32.u64 %0, t; }"
        : "=r"(a) : "l"(p));
    return a;
}

#define SW128(o) ((o) ^ (((o) >> 3) & 0x70))

__device__ __forceinline__ void cp_async16(uint32_t dst, const void* src) {
    asm volatile("cp.async.cg.shared.global [%0], [%1], 16;"
                 :: "r"(dst), "l"(src) : "memory");
}
__device__ __forceinline__ void cp_commit() {
    asm volatile("cp.async.commit_group;" ::: "memory");
}
template <int N>
__device__ __forceinline__ void cp_wait() {
    asm volatile("cp.async.wait_group %0;" :: "n"(N) : "memory");
}

__device__ __forceinline__ void ldm_x4(uint32_t* r, uint32_t a) {
    asm volatile("ldmatrix.sync.aligned.m8n8.x4.shared.b16 {%0,%1,%2,%3}, [%4];"
                 : "=r"(r[0]), "=r"(r[1]), "=r"(r[2]), "=r"(r[3]) : "r"(a));
}

__device__ __forceinline__ void mma16816(float* d, const uint32_t* a, const uint32_t* b) {
    asm volatile(
        "mma.sync.aligned.m16n8k16.row.col.f32.f16.f16.f32 "
        "{%0,%1,%2,%3}, {%4,%5,%6,%7}, {%8,%9}, {%0,%1,%2,%3};"
        : "+f"(d[0]), "+f"(d[1]), "+f"(d[2]), "+f"(d[3])
        : "r"(a[0]), "r"(a[1]), "r"(a[2]), "r"(a[3]), "r"(b[0]), "r"(b[1]));
}

// pack 8 floats -> one uint4 of fp16
__device__ __forceinline__ uint4 pack8_h(const float* v) {
    uint32_t u[4];
#pragma unroll
    for (int j = 0; j < 4; j++) {
        unsigned short a = __half_as_ushort(__float2half_rn(v[2*j]));
        unsigned short b = __half_as_ushort(__float2half_rn(v[2*j+1]));
        u[j] = (uint32_t)a | ((uint32_t)b << 16);
    }
    return make_uint4(u[0], u[1], u[2], u[3]);
}

// ---------------------------------------------------------------------------
// fp32 -> fp16 (scaled); skip rows >= ceil128(len).
// Block: 256 thr, 2 rows. grid (S/2, B)
// ---------------------------------------------------------------------------
__global__ __launch_bounds__(256) void conv_h_kernel(
    const float* __restrict__ src, __half* __restrict__ dst,
    const int* __restrict__ lens, float scale)
{
    int b = blockIdx.y;
    int q0 = blockIdx.x * 2;
    if (q0 >= ((lens[b] + 127) & ~127)) return;
    int tid = threadIdx.x;
    int row = q0 + (tid >> 7);
    int c8  = tid & 127;
    size_t i = ((size_t)b * SQ_ + row) * (D_ / 8) + c8;
    float4 a = ((const float4*)src)[2*i];
    float4 c = ((const float4*)src)[2*i+1];
    float v[8] = {a.x*scale, a.y*scale, a.z*scale, a.w*scale,
                  c.x*scale, c.y*scale, c.z*scale, c.w*scale};
    ((uint4*)dst)[i] = pack8_h(v);
}

// ---------------------------------------------------------------------------
// V transpose (high only): V[b,k,n] -> Vth[b,n,k]; skip k0 >= ceil64(klen)
// ---------------------------------------------------------------------------
__global__ __launch_bounds__(256) void conv_vt_kernel(
    const float* __restrict__ V, __half* __restrict__ Vth,
    const int* __restrict__ klens)
{
    int b  = blockIdx.z;
    int k0 = blockIdx.y * 64;
    if (k0 >= ((klens[b] + 63) & ~63)) return;
    __shared__ float tile[64][33];
    int n0 = blockIdx.x * 32;
    int tid = threadIdx.x;

    const float* Vb = V + (size_t)b * SK_ * DV_;
    int c = tid & 31;
    int r0 = tid >> 5;
#pragma unroll
    for (int p = 0; p < 8; p++) {
        int r = r0 + p * 8;
        tile[r][c] = Vb[(size_t)(k0 + r) * DV_ + n0 + c];
    }
    __syncthreads();

    int n  = tid >> 3;
    int kg = tid & 7;
    float v[8];
#pragma unroll
    for (int i = 0; i < 8; i++) v[i] = tile[kg * 8 + i][n];
    size_t off = (size_t)b * DV_ * SK_ + (size_t)(n0 + n) * SK_ + k0 + kg * 8;
    *(uint4*)(Vth + off) = pack8_h(v);
}

// ---------------------------------------------------------------------------
// Masked softmax (fp32 W in-place) + fp16 Wh; shfl-based reductions (2 bars),
// zero fast-path for fully-masked rows; Wh writes limited to GEMM2's reads.
// ---------------------------------------------------------------------------
__global__ __launch_bounds__(256) void softmax_split_kernel(
    float* __restrict__ W, __half* __restrict__ Wh,
    const int* __restrict__ qlens, const int* __restrict__ klens)
{
    int q = blockIdx.x;
    int b = blockIdx.y;
    float* row = W + ((size_t)b * SQ_ + q) * SK_;

    int qlen = qlens[b];
    int klen = klens[b];
    int valid = (q < qlen) ? min(klen, q + 1) : 0;

    int tid = threadIdx.x;
    int lane = tid & 31;
    int wrp = tid >> 5;
    int j0 = tid * 8;

    int qceil = (qlen + 127) & ~127;
    int kmaxt = min(klen, ((q >> 7) + 1) << 7);
    bool wh_write = (q < qceil) && (j0 < min(SK_, kmaxt + 64));

    if (valid == 0) {
        // fully masked row: weights are exactly zero
        float4 z = make_float4(0.f, 0.f, 0.f, 0.f);
        ((float4*)row)[2*tid] = z;
        ((float4*)row)[2*tid+1] = z;
        if (wh_write) {
            float v0[8] = {0,0,0,0,0,0,0,0};
            *(uint4*)(Wh + ((size_t)b * SQ_ + q) * SK_ + j0) = pack8_h(v0);
        }
        return;
    }

    float v[8] = {0.f, 0.f, 0.f, 0.f, 0.f, 0.f, 0.f, 0.f};
    if (j0 < valid) {
        float4 x0 = ((const float4*)row)[2*tid];
        float4 x1 = ((const float4*)row)[2*tid+1];
        v[0]=x0.x; v[1]=x0.y; v[2]=x0.z; v[3]=x0.w;
        v[4]=x1.x; v[5]=x1.y; v[6]=x1.z; v[7]=x1.w;
    }

    __shared__ float smax[8], ssum[8];

    float mx = -INFINITY;
#pragma unroll
    for (int i = 0; i < 8; i++)
        if (j0 + i < valid) mx = fmaxf(mx, v[i]);
#pragma unroll
    for (int off = 16; off > 0; off >>= 1)
        mx = fmaxf(mx, __shfl_xor_sync(0xffffffffu, mx, off));
    if (lane == 0) smax[wrp] = mx;
    __syncthreads();
#pragma unroll
    for (int w = 0; w < 8; w++) mx = fmaxf(mx, smax[w]);

    float sum = 0.f;
#pragma unroll
    for (int i = 0; i < 8; i++) {
        float e = (j0 + i < valid) ? expf(v[i] - mx) : 0.f;
        v[i] = e;
        sum += e;
    }
#pragma unroll
    for (int off = 16; off > 0; off >>= 1)
        sum += __shfl_xor_sync(0xffffffffu, sum, off);
    if (lane == 0) ssum[wrp] = sum;
    __syncthreads();
    sum = 0.f;
#pragma unroll
    for (int w = 0; w < 8; w++) sum += ssum[w];

    float inv = (sum > 0.f) ? (1.f / sum) : 0.f;
#pragma unroll
    for (int i = 0; i < 8; i++) v[i] *= inv;

    ((float4*)row)[2*tid]   = make_float4(v[0], v[1], v[2], v[3]);
    ((float4*)row)[2*tid+1] = make_float4(v[4], v[5], v[6], v[7]);

    if (wh_write)
        *(uint4*)(Wh + ((size_t)b * SQ_ + q) * SK_ + j0) = pack8_h(v);
}

// ---------------------------------------------------------------------------
// HMMA NT GEMM: C = A x B^T, fp16 in, fp32 accum.
// CTA 128x128, 4 warps (64x64 each), K-chunk 64, 2-stage cp.async (64KB).
// mode 0: scores  — triangular 1D grid, skip masked tiles
// mode 1: context — K-loop bound ceil64(min(klen, m0+128)); zero if m0>=qlen
// ---------------------------------------------------------------------------
#define STAGE_BYTES 32768
#define GEMM_SMEM (2 * STAGE_BYTES)

__global__ __launch_bounds__(128, 2) void gemm_hmma(
    const __half* __restrict__ A,
    const __half* __restrict__ Bm,
    float* __restrict__ C, int Kb, int ldc, int M, int N,
    const int* __restrict__ qlens, const int* __restrict__ klens, int mode)
{
    extern __shared__ __align__(1024) char smem[];

    int b = blockIdx.z;
    int m0, n0;
    if (mode == 0) {
        int i = blockIdx.x;
        int mt = (int)((sqrtf(8.0f * i + 1.0f) - 1.0f) * 0.5f);
        while ((mt + 1) * (mt + 2) / 2 <= i) mt++;
        while (mt * (mt + 1) / 2 > i) mt--;
        int nt = i - mt * (mt + 1) / 2;
        m0 = mt * 128; n0 = nt * 128;
    } else {
        m0 = blockIdx.y * 128;
        n0 = blockIdx.x * 128;
    }
    int qlen = qlens[b];
    int klen = klens[b];

    int tid = threadIdx.x;
    int lane = tid & 31;
    int wid = tid >> 5;

    A  += (size_t)b * M * Kb + (size_t)m0 * Kb;
    Bm += (size_t)b * N * Kb + (size_t)n0 * Kb;
    C  += (size_t)b * M * ldc + (size_t)m0 * ldc + n0;

    int nch = Kb >> 6;
    int kmax = min(klen, m0 + 128);
    if (mode == 0) {
        if (m0 >= qlen || n0 >= kmax) return;
    } else {
        if (m0 >= qlen) {
            for (int i = tid; i < 4096; i += 128) {
                int r = i >> 5, c4 = i & 31;
                *(float4*)(C + (size_t)r * ldc + c4 * 4) = make_float4(0.f, 0.f, 0.f, 0.f);
            }
            return;
        }
        nch = min(nch, (kmax + 63) >> 6);
    }

    uint32_t sb = smem_u32(smem);

    int warp_m = (wid >> 1) * 64;
    int warp_n = (wid & 1) * 64;
    int a_row = warp_m + (lane & 15);
    int a_cb  = (lane >> 4) * 16;
    int b_row = warp_n + (lane & 7) + ((lane >> 4) & 1) * 8;
    int b_cb  = ((lane >> 3) & 1) * 16;

    float acc[4][8][4];
#pragma unroll
    for (int mi = 0; mi < 4; mi++)
#pragma unroll
        for (int ni = 0; ni < 8; ni++)
#pragma unroll
            for (int r = 0; r < 4; r++) acc[mi][ni][r] = 0.f;

    auto load_tile = [&](int s, int c) {
        uint32_t abase = sb + s * STAGE_BYTES;
        const __half* Ac = A + c * 64;
        const __half* Bc = Bm + c * 64;
#pragma unroll
        for (int i = 0; i < 8; i++) {
            int u = tid + i * 128;
            int row = u >> 3, c8 = u & 7;
            size_t goff = (size_t)row * Kb + c8 * 8;
            uint32_t off = SW128((uint32_t)(row * 128 + c8 * 16));
            cp_async16(abase + off, Ac + goff);
            cp_async16(abase + 16384 + off, Bc + goff);
        }
    };

    load_tile(0, 0);
    cp_commit();

    for (int c = 0; c < nch; c++) {
        cp_wait<0>();
        __syncthreads();

        if (c + 1 < nch) { load_tile((c + 1) & 1, c + 1); cp_commit(); }

        uint32_t abase = sb + (c & 1) * STAGE_BYTES;
        uint32_t bbase = abase + 16384;

#pragma unroll
        for (int ks = 0; ks < 4; ks++) {
            uint32_t af[4][4], bf[4][4];
#pragma unroll
            for (int mi = 0; mi < 4; mi++) {
                uint32_t o = (uint32_t)((a_row + mi * 16) * 128 + ks * 32 + a_cb);
                ldm_x4(af[mi], abase + SW128(o));
            }
#pragma unroll
            for (int nj = 0; nj < 4; nj++) {
                uint32_t o = (uint32_t)((b_row + nj * 16) * 128 + ks * 32 + b_cb);
                ldm_x4(bf[nj], bbase + SW128(o));
            }
#pragma unroll
            for (int mi = 0; mi < 4; mi++)
#pragma unroll
                for (int ni = 0; ni < 8; ni++)
                    mma16816(acc[mi][ni], af[mi], &bf[ni >> 1][(ni & 1) * 2]);
        }
    }

    // epilogue
#pragma unroll
    for (int mi = 0; mi < 4; mi++) {
        int r0 = warp_m + mi * 16 + (lane >> 2);
#pragma unroll
        for (int ni = 0; ni < 8; ni++) {
            int cc = warp_n + ni * 8 + (lane & 3) * 2;
            *(float2*)(C + (size_t)r0 * ldc + cc) =
                make_float2(acc[mi][ni][0], acc[mi][ni][1]);
            *(float2*)(C + (size_t)(r0 + 8) * ldc + cc) =
                make_float2(acc[mi][ni][2], acc[mi][ni][3]);
        }
    }
}

// ---------------------------------------------------------------------------
extern "C" void kernel_launch(void* const* d_in, const int* in_sizes, int n_in,
                              void* d_out, int out_size)
{
    const float* Q  = (const float*)d_in[0];
    const float* Kk = (const float*)d_in[1];
    const float* V  = (const float*)d_in[2];
    const int* qlens = (const int*)d_in[3];
    const int* klens = (const int*)d_in[4];

    float* ctx = (float*)d_out;                              // (B, SQ, DV)
    float* W   = (float*)d_out + (size_t)B_ * SQ_ * DV_;     // (B, SQ, SK)

    void *pQh, *pKh, *pVth, *pWh;
    cudaGetSymbolAddress(&pQh, g_Qh);
    cudaGetSymbolAddress(&pKh, g_Kh);
    cudaGetSymbolAddress(&pVth, g_Vth);
    cudaGetSymbolAddress(&pWh, g_Wh);
    cudaFuncSetAttribute(gemm_hmma,
                         cudaFuncAttributeMaxDynamicSharedMemorySize, GEMM_SMEM);

    // conversions (mask-aware row skipping)
    dim3 gq(SQ_ / 2, B_);
    conv_h_kernel<<<gq, 256>>>(Q, (__half*)pQh, qlens, 0.03125f);
    conv_h_kernel<<<gq, 256>>>(Kk, (__half*)pKh, klens, 1.0f);
    dim3 gv(DV_ / 32, SK_ / 64, B_);
    conv_vt_kernel<<<gv, 256>>>(V, (__half*)pVth, klens);

    // S = Qh Kh^T -> weights region (fp32), triangular grid
    dim3 g1(16 * 17 / 2, 1, B_);
    gemm_hmma<<<g1, 128, GEMM_SMEM>>>(
        (const __half*)pQh, (const __half*)pKh, W,
        D_, SK_, SQ_, SK_, qlens, klens, 0);

    // masked softmax + fp16 weights
    dim3 gs(SQ_, B_);
    softmax_split_kernel<<<gs, 256>>>(W, (__half*)pWh, qlens, klens);

    // context = Wh Vth^T
    dim3 g2(DV_ / 128, SQ_ / 128, B_);
    gemm_hmma<<<g2, 128, GEMM_SMEM>>>(
        (const __half*)pWh, (const __half*)pVth, ctx,
        SK_, DV_, SQ_, DV_, qlens, klens, 1);
}